// round 1
// baseline (speedup 1.0000x reference)
#include <cuda_runtime.h>
#include <cuda_bf16.h>

#define T_ 32
#define B_ 32
#define TB 1024
#define MAP 517
#define FLAT 132352   // 517*256
#define NACT 5

// ---------------- scratch (device globals; no cudaMalloc allowed) ----------------
__device__ float g_Wt[FLAT * 128];      // [f][j]  j<64 pol rows, j>=64 val rows  (67.8MB)
__device__ float g_fcwt[1024 * 512];    // [k][j]
__device__ float g_c1o[TB * 32 * 225];  // conv1 out (TB,32,15,15)
__device__ float g_c2o[TB * 64 * 36];   // conv2 out (TB,64,6,6)
__device__ float g_c3o[TB * 1024];      // conv3 out flattened (TB,1024)
__device__ float g_h[TB * MAP];         // per-step feature+onehot (TB,517)
__device__ float g_acc0[B_ * 128];      // initial accumulator from state0
__device__ int   g_lastw[B_ * 256];     // last writer step per cell (-2 state0, -1 zero)

// ---------------- transpose big head weights: Wt[f*128+j] ----------------
__global__ void k_transW(const float* __restrict__ pol, const float* __restrict__ val) {
    __shared__ float tile[32][33];
    int f = blockIdx.x * 32 + threadIdx.x;
    int j = blockIdx.y * 32 + threadIdx.y;
    const float* src = (j < 64) ? (pol + (size_t)j * FLAT) : (val + (size_t)(j - 64) * FLAT);
    tile[threadIdx.y][threadIdx.x] = src[f];
    __syncthreads();
    int fo = blockIdx.x * 32 + threadIdx.y;
    int jo = blockIdx.y * 32 + threadIdx.x;
    g_Wt[(size_t)fo * 128 + jo] = tile[threadIdx.x][threadIdx.y];
}

// ---------------- transpose fc weights: fcwt[k*512+j] = fc_w[j*1024+k] ----------------
__global__ void k_transFC(const float* __restrict__ fcw) {
    __shared__ float tile[32][33];
    int k = blockIdx.x * 32 + threadIdx.x;  // 0..1023
    int j = blockIdx.y * 32 + threadIdx.y;  // 0..511
    tile[threadIdx.y][threadIdx.x] = fcw[j * 1024 + k];
    __syncthreads();
    int ko = blockIdx.x * 32 + threadIdx.y;
    int jo = blockIdx.y * 32 + threadIdx.x;
    g_fcwt[ko * 512 + jo] = tile[threadIdx.x][threadIdx.y];
}

// ---------------- conv1: (3,64,64) k8 s4 -> (32,15,15), relu ----------------
__global__ __launch_bounds__(256) void k_conv1(const float* __restrict__ img,
                                               const float* __restrict__ w,
                                               const float* __restrict__ bias) {
    extern __shared__ float sh[];
    float* simg = sh;          // 3*64*64 = 12288
    float* sw   = sh + 12288;  // 32*3*64 = 6144
    int ib = blockIdx.x;
    const float* ip = img + (size_t)ib * 12288;
    for (int i = threadIdx.x; i < 12288; i += 256) simg[i] = ip[i];
    for (int i = threadIdx.x; i < 6144;  i += 256) sw[i]   = w[i];
    __syncthreads();
    for (int idx = threadIdx.x; idx < 32 * 225; idx += 256) {
        int oc = idx / 225, sp = idx % 225, oy = sp / 15, ox = sp % 15;
        float acc = bias[oc];
        const float* wp = sw + oc * 192;
        #pragma unroll
        for (int c = 0; c < 3; c++) {
            const float* irow = simg + c * 4096 + (oy * 4) * 64 + ox * 4;
            const float* wr = wp + c * 64;
            #pragma unroll
            for (int ky = 0; ky < 8; ky++)
                #pragma unroll
                for (int kx = 0; kx < 8; kx++)
                    acc += irow[ky * 64 + kx] * wr[ky * 8 + kx];
        }
        g_c1o[(size_t)ib * 7200 + idx] = fmaxf(acc, 0.f);
    }
}

// ---------------- conv2: (32,15,15) k4 s2 -> (64,6,6), relu ----------------
__global__ __launch_bounds__(256) void k_conv2(const float* __restrict__ w,
                                               const float* __restrict__ bias) {
    extern __shared__ float sh[];
    float* sin_ = sh;         // 32*225 = 7200
    float* sw   = sh + 7200;  // 64*8*16 = 8192
    int ib = blockIdx.x;
    for (int i = threadIdx.x; i < 7200; i += 256) sin_[i] = g_c1o[(size_t)ib * 7200 + i];
    float acc[9];
    int oc[9], oy[9], ox[9];
    #pragma unroll
    for (int o = 0; o < 9; o++) {
        int idx = threadIdx.x + o * 256;  // < 2304
        oc[o] = idx / 36; int sp = idx % 36; oy[o] = sp / 6; ox[o] = sp % 6;
        acc[o] = bias[oc[o]];
    }
    for (int icb = 0; icb < 4; icb++) {
        __syncthreads();
        for (int i = threadIdx.x; i < 8192; i += 256) {
            int o2 = i >> 7; int rest = i & 127;
            sw[i] = w[o2 * 512 + icb * 128 + rest];
        }
        __syncthreads();
        #pragma unroll
        for (int o = 0; o < 9; o++) {
            const float* wp = sw + oc[o] * 128;
            float a = acc[o];
            #pragma unroll
            for (int icl = 0; icl < 8; icl++) {
                const float* ipp = sin_ + (icb * 8 + icl) * 225 + (oy[o] * 2) * 15 + ox[o] * 2;
                const float* wr = wp + icl * 16;
                #pragma unroll
                for (int ky = 0; ky < 4; ky++)
                    #pragma unroll
                    for (int kx = 0; kx < 4; kx++)
                        a += ipp[ky * 15 + kx] * wr[ky * 4 + kx];
            }
            acc[o] = a;
        }
    }
    #pragma unroll
    for (int o = 0; o < 9; o++) {
        int idx = threadIdx.x + o * 256;
        g_c2o[(size_t)ib * 2304 + idx] = fmaxf(acc[o], 0.f);
    }
}

// ---------------- conv3: (64,6,6) k3 s1 -> (64,4,4), relu ----------------
__global__ __launch_bounds__(256) void k_conv3(const float* __restrict__ w,
                                               const float* __restrict__ bias) {
    extern __shared__ float sh[];
    float* sin_ = sh;         // 64*36 = 2304
    float* sw   = sh + 2304;  // 64*16*9 = 9216
    int ib = blockIdx.x;
    for (int i = threadIdx.x; i < 2304; i += 256) sin_[i] = g_c2o[(size_t)ib * 2304 + i];
    float acc[4];
    int oc[4], oy[4], ox[4];
    #pragma unroll
    for (int o = 0; o < 4; o++) {
        int idx = threadIdx.x + o * 256;  // < 1024
        oc[o] = idx / 16; int sp = idx % 16; oy[o] = sp / 4; ox[o] = sp % 4;
        acc[o] = bias[oc[o]];
    }
    for (int icb = 0; icb < 4; icb++) {
        __syncthreads();
        for (int i = threadIdx.x; i < 9216; i += 256) {
            int o2 = i / 144; int r = i % 144;
            sw[i] = w[o2 * 576 + icb * 144 + r];
        }
        __syncthreads();
        #pragma unroll
        for (int o = 0; o < 4; o++) {
            const float* wp = sw + oc[o] * 144;
            float a = acc[o];
            #pragma unroll
            for (int icl = 0; icl < 16; icl++) {
                const float* ipp = sin_ + (icb * 16 + icl) * 36 + oy[o] * 6 + ox[o];
                const float* wr = wp + icl * 9;
                #pragma unroll
                for (int ky = 0; ky < 3; ky++)
                    #pragma unroll
                    for (int kx = 0; kx < 3; kx++)
                        a += ipp[ky * 6 + kx] * wr[ky * 3 + kx];
            }
            acc[o] = a;
        }
    }
    #pragma unroll
    for (int o = 0; o < 4; o++) {
        int idx = threadIdx.x + o * 256;
        g_c3o[(size_t)ib * 1024 + idx] = fmaxf(acc[o], 0.f);
    }
}

// ---------------- fc + relu + onehot concat -> g_h ----------------
__global__ __launch_bounds__(512) void k_fc(const float* __restrict__ bias,
                                            const int* __restrict__ lastact) {
    __shared__ float xs[1024];
    int ib = blockIdx.x;
    for (int i = threadIdx.x; i < 1024; i += 512) xs[i] = g_c3o[(size_t)ib * 1024 + i];
    __syncthreads();
    int j = threadIdx.x;
    float acc = bias[j];
    const float* wp = g_fcwt + j;
    #pragma unroll 8
    for (int k = 0; k < 1024; k++) acc += wp[k * 512] * xs[k];
    g_h[(size_t)ib * MAP + j] = fmaxf(acc, 0.f);
    if (j < NACT) g_h[(size_t)ib * MAP + 512 + j] = (lastact[ib] == j) ? 1.f : 0.f;
}

// ---------------- zero acc0 ----------------
__global__ void k_zero() { g_acc0[blockIdx.x * 128 + threadIdx.x] = 0.f; }

// ---------------- acc0 = W_all @ state0_flat  (general correctness; zeros in bench) ------
__global__ __launch_bounds__(128) void k_acc0(const float* __restrict__ s0) {
    extern __shared__ float s0s[];  // 32 * 512 floats
    int f0 = blockIdx.x * 512;
    int j = threadIdx.x;
    for (int i = threadIdx.x; i < 32 * 512; i += 128) {
        int b = i >> 9; int fo = i & 511; int f = f0 + fo;
        s0s[i] = (f < FLAT) ? s0[(size_t)b * FLAT + f] : 0.f;
    }
    __syncthreads();
    float part[32];
    #pragma unroll
    for (int b = 0; b < 32; b++) part[b] = 0.f;
    int fmax = FLAT - f0; if (fmax > 512) fmax = 512;
    for (int fo = 0; fo < fmax; fo++) {
        float w = g_Wt[(size_t)(f0 + fo) * 128 + j];
        #pragma unroll
        for (int b = 0; b < 32; b++) part[b] += w * s0s[b * 512 + fo];
    }
    #pragma unroll
    for (int b = 0; b < 32; b++) atomicAdd(&g_acc0[b * 128 + j], part[b]);
}

// ---------------- sequential scan + incremental head GEMM ----------------
__global__ __launch_bounds__(512) void k_scan(const float* __restrict__ done,
                                              const int* __restrict__ pos,
                                              const float* __restrict__ s0,
                                              const float* __restrict__ pb1,
                                              const float* __restrict__ vb1,
                                              const float* __restrict__ pw2,
                                              const float* __restrict__ pb2,
                                              const float* __restrict__ vw2,
                                              const float* __restrict__ vb2,
                                              float* __restrict__ logits,
                                              float* __restrict__ vout) {
    __shared__ float delta[520];
    __shared__ float accs[128];
    __shared__ float th[128];
    __shared__ float partials[512];
    __shared__ int lastw[256];
    int b = blockIdx.x;
    int tid = threadIdx.x;
    int j = tid & 127, kq = tid >> 7;
    if (tid < 256) lastw[tid] = -2;
    if (tid < 128) accs[tid] = g_acc0[b * 128 + tid];
    for (int t = 0; t < T_; t++) {
        __syncthreads();
        float dn = done[t * B_ + b];
        if (dn != 0.0f) {
            if (tid < 128) accs[tid] = 0.f;
            if (tid < 256) lastw[tid] = -1;
        }
        __syncthreads();
        int r = t * B_ + b;
        int cell = pos[r * 2] * 16 + pos[r * 2 + 1];
        int code = lastw[cell];
        const float* hrow = g_h + (size_t)r * MAP;
        for (int k = tid; k < MAP; k += 512) {
            float old = 0.f;
            if (code >= 0)       old = g_h[(size_t)(code * B_ + b) * MAP + k];
            else if (code == -2) old = s0[(size_t)b * FLAT + k * 256 + cell];
            delta[k] = hrow[k] - old;
        }
        __syncthreads();
        float p = 0.f;
        const float* wtp = g_Wt + (size_t)cell * 128 + j;
        for (int k = kq; k < MAP; k += 4)
            p += wtp[(size_t)k * 32768] * delta[k];
        partials[tid] = p;
        __syncthreads();
        if (tid < 128) {
            float a = accs[tid] + partials[tid] + partials[tid + 128] +
                      partials[tid + 256] + partials[tid + 384];
            accs[tid] = a;
            float bb = (tid < 64) ? pb1[tid] : vb1[tid - 64];
            th[tid] = tanhf(a + bb);
        }
        __syncthreads();
        if (tid < NACT) {
            float s = pb2[tid];
            #pragma unroll
            for (int q = 0; q < 64; q++) s += th[q] * pw2[tid * 64 + q];
            logits[r * NACT + tid] = s;
        } else if (tid == 8) {
            float s = vb2[0];
            #pragma unroll
            for (int q = 0; q < 64; q++) s += th[64 + q] * vw2[q];
            vout[r] = s;
        } else if (tid == 16) {
            lastw[cell] = t;
        }
    }
    __syncthreads();
    if (tid < 256) g_lastw[b * 256 + tid] = lastw[tid];
}

// ---------------- reconstruct final_state ----------------
__global__ __launch_bounds__(256) void k_final(const float* __restrict__ s0,
                                               float* __restrict__ out) {
    int b = blockIdx.y;
    int f = blockIdx.x * 256 + threadIdx.x;  // 517*256 blocks.x covers exactly
    int cell = f & 255, k = f >> 8;
    int code = g_lastw[b * 256 + cell];
    float v;
    if (code >= 0)       v = g_h[(size_t)(code * B_ + b) * MAP + k];
    else if (code == -2) v = s0[(size_t)b * FLAT + f];
    else                 v = 0.f;
    out[(size_t)b * FLAT + f] = v;
}

// ---------------- host ----------------
extern "C" void kernel_launch(void* const* d_in, const int* in_sizes, int n_in,
                              void* d_out, int out_size) {
    const float* image  = (const float*)d_in[0];
    const int*   lact   = (const int*)  d_in[1];
    const int*   pos    = (const int*)  d_in[2];
    const float* done   = (const float*)d_in[3];
    const float* state0 = (const float*)d_in[4];
    const float* c1w = (const float*)d_in[5];
    const float* c1b = (const float*)d_in[6];
    const float* c2w = (const float*)d_in[7];
    const float* c2b = (const float*)d_in[8];
    const float* c3w = (const float*)d_in[9];
    const float* c3b = (const float*)d_in[10];
    const float* fcw = (const float*)d_in[11];
    const float* fcb = (const float*)d_in[12];
    const float* pw1 = (const float*)d_in[13];
    const float* pb1 = (const float*)d_in[14];
    const float* pw2 = (const float*)d_in[15];
    const float* pb2 = (const float*)d_in[16];
    const float* vw1 = (const float*)d_in[17];
    const float* vb1 = (const float*)d_in[18];
    const float* vw2 = (const float*)d_in[19];
    const float* vb2 = (const float*)d_in[20];

    float* out_logits = (float*)d_out;                   // 1024*5
    float* out_v      = (float*)d_out + TB * NACT;       // 1024
    float* out_state  = (float*)d_out + TB * NACT + TB;  // 32*132352

    cudaFuncSetAttribute(k_conv1, cudaFuncAttributeMaxDynamicSharedMemorySize, 80 * 1024);
    cudaFuncSetAttribute(k_conv2, cudaFuncAttributeMaxDynamicSharedMemorySize, 64 * 1024);
    cudaFuncSetAttribute(k_conv3, cudaFuncAttributeMaxDynamicSharedMemorySize, 48 * 1024);
    cudaFuncSetAttribute(k_acc0,  cudaFuncAttributeMaxDynamicSharedMemorySize, 68 * 1024);

    // weight transposes (independent of data path)
    k_transW <<<dim3(FLAT / 32, 4), dim3(32, 32)>>>(pw1, vw1);
    k_transFC<<<dim3(32, 16),       dim3(32, 32)>>>(fcw);

    // CNN feature path
    k_conv1<<<TB, 256, (12288 + 6144) * 4>>>(image, c1w, c1b);
    k_conv2<<<TB, 256, (7200 + 8192) * 4>>>(c2w, c2b);
    k_conv3<<<TB, 256, (2304 + 9216) * 4>>>(c3w, c3b);
    k_fc   <<<TB, 512>>>(fcb, lact);

    // initial accumulator from state0 (general; zeros in this bench)
    k_zero <<<32, 128>>>();
    k_acc0 <<<(FLAT + 511) / 512, 128, 32 * 512 * 4>>>(state0);

    // sequential incremental scan producing logits & values
    k_scan <<<B_, 512>>>(done, pos, state0, pb1, vb1, pw2, pb2, vw2, vb2,
                         out_logits, out_v);

    // final state reconstruction
    k_final<<<dim3(FLAT / 256, B_), 256>>>(state0, out_state);

    (void)in_sizes; (void)n_in; (void)out_size;
}

// round 2
// speedup vs baseline: 1.6337x; 1.6337x over previous
#include <cuda_runtime.h>
#include <cuda_bf16.h>

#define T_ 32
#define B_ 32
#define TB 1024
#define MAP 517
#define FLAT 132352   // 517*256
#define NACT 5

// ---------------- scratch (device globals; no cudaMalloc allowed) ----------------
__device__ float g_Wt[FLAT * 128];      // [f][j]  j<64 pol rows, j>=64 val rows  (67.8MB)
__device__ float g_fcwt[1024 * 512];    // [k][j]
__device__ float g_c1o[TB * 32 * 225];  // conv1 out (TB,32,15,15)
__device__ float g_c2o[TB * 64 * 36];   // conv2 out (TB,64,6,6)
__device__ float g_c3o[TB * 1024];      // conv3 out flattened (TB,1024)
__device__ float g_h[TB * MAP];         // per-step feature+onehot (TB,517)
__device__ float g_acc0[B_ * 128];      // initial accumulator from state0
__device__ int   g_lastw[B_ * 256];     // last writer step per cell (-2 state0, -1 zero)

// ---------------- transpose big head weights: Wt[f*128+j] ----------------
__global__ void k_transW(const float* __restrict__ pol, const float* __restrict__ val) {
    __shared__ float tile[32][33];
    int f = blockIdx.x * 32 + threadIdx.x;
    int j = blockIdx.y * 32 + threadIdx.y;
    const float* src = (j < 64) ? (pol + (size_t)j * FLAT) : (val + (size_t)(j - 64) * FLAT);
    tile[threadIdx.y][threadIdx.x] = src[f];
    __syncthreads();
    int fo = blockIdx.x * 32 + threadIdx.y;
    int jo = blockIdx.y * 32 + threadIdx.x;
    g_Wt[(size_t)fo * 128 + jo] = tile[threadIdx.x][threadIdx.y];
}

// ---------------- transpose fc weights: fcwt[k*512+j] = fc_w[j*1024+k] ----------------
__global__ void k_transFC(const float* __restrict__ fcw) {
    __shared__ float tile[32][33];
    int k = blockIdx.x * 32 + threadIdx.x;  // 0..1023
    int j = blockIdx.y * 32 + threadIdx.y;  // 0..511
    tile[threadIdx.y][threadIdx.x] = fcw[j * 1024 + k];
    __syncthreads();
    int ko = blockIdx.x * 32 + threadIdx.y;
    int jo = blockIdx.y * 32 + threadIdx.x;
    g_fcwt[ko * 512 + jo] = tile[threadIdx.x][threadIdx.y];
}

// ================= conv1: (3,64,64) k8 s4 -> (32,15,15), relu ==================
// Register-tiled: thread computes 8 oc x 5 ox. 192 threads, 1 image/block.
__global__ __launch_bounds__(192) void k_conv1(const float* __restrict__ img,
                                               const float* __restrict__ w,
                                               const float* __restrict__ bias) {
    extern __shared__ float sh[];
    float* simg = sh;                 // 12288
    float* swt  = sh + 12288;         // [32][193] = 6176
    int ib = blockIdx.x;
    int tid = threadIdx.x;
    const float* ip = img + (size_t)ib * 12288;
    for (int i = tid; i < 12288; i += 192) simg[i] = ip[i];
    // swt[oc][k] = w[oc*192+k], padded rows (193)
    #pragma unroll
    for (int r = 0; r < 32; r++) swt[r * 193 + tid] = w[r * 192 + tid];
    __syncthreads();

    int ocg = tid & 3;          // 4 groups of 8 oc
    int ntile = tid >> 2;       // 0..47, active < 45
    int oy = ntile / 3, oxb = (ntile % 3) * 5;
    int ibase = oy * 256 + oxb * 4;   // oy*4*64 + oxb*4
    bool active = (ntile < 45);

    float acc[8][5];
    #pragma unroll
    for (int m = 0; m < 8; m++)
        #pragma unroll
        for (int i = 0; i < 5; i++) acc[m][i] = 0.f;

    const float* wrow0 = swt + (ocg * 8) * 193;
    #pragma unroll
    for (int c = 0; c < 3; c++) {
        #pragma unroll
        for (int ky = 0; ky < 8; ky++) {
            int off = c * 4096 + ky * 64 + ibase;
            float row[24];
            #pragma unroll
            for (int q = 0; q < 24; q++) row[q] = simg[off + q];
            int kb = c * 64 + ky * 8;
            #pragma unroll
            for (int kx = 0; kx < 8; kx++) {
                float wv[8];
                #pragma unroll
                for (int m = 0; m < 8; m++) wv[m] = wrow0[m * 193 + kb + kx];
                #pragma unroll
                for (int m = 0; m < 8; m++)
                    #pragma unroll
                    for (int i = 0; i < 5; i++)
                        acc[m][i] += wv[m] * row[kx + 4 * i];
            }
        }
    }
    if (active) {
        #pragma unroll
        for (int m = 0; m < 8; m++) {
            int oc = ocg * 8 + m;
            float bb = bias[oc];
            #pragma unroll
            for (int i = 0; i < 5; i++)
                g_c1o[(size_t)ib * 7200 + oc * 225 + oy * 15 + oxb + i] =
                    fmaxf(acc[m][i] + bb, 0.f);
        }
    }
}

// ================= conv2: (32,15,15) k4 s2 -> (64,6,6), relu ==================
// Register-tiled: thread computes 8 oc x 6 ox (one oy row). 4 images/block, 192 threads.
__global__ __launch_bounds__(192) void k_conv2(const float* __restrict__ w,
                                               const float* __restrict__ bias) {
    extern __shared__ float sh[];
    float* sin_ = sh;            // 4*7200 = 28800
    float* swt  = sh + 28800;    // [64][129] = 8256
    int ib4 = blockIdx.x;        // 256 blocks
    int tid = threadIdx.x;
    for (int i = tid; i < 28800; i += 192)
        sin_[i] = g_c1o[(size_t)ib4 * 28800 + i];

    int ocg = tid & 7;           // 8 groups of 8 oc
    int ntile = tid >> 3;        // 0..23 = 4 img x 6 oy
    int img_l = ntile / 6, oy = ntile % 6;
    int base_in = img_l * 7200 + oy * 30;

    float acc[8][6];
    #pragma unroll
    for (int m = 0; m < 8; m++)
        #pragma unroll
        for (int i = 0; i < 6; i++) acc[m][i] = 0.f;

    for (int cb = 0; cb < 4; cb++) {
        __syncthreads();
        for (int i = tid; i < 8192; i += 192) {
            int oc = i >> 7, kk = i & 127;
            swt[oc * 129 + kk] = w[oc * 512 + cb * 128 + kk];
        }
        __syncthreads();
        const float* wrow0 = swt + (ocg * 8) * 129;
        #pragma unroll
        for (int icl = 0; icl < 8; icl++) {
            int pbase = base_in + (cb * 8 + icl) * 225;
            #pragma unroll
            for (int ky = 0; ky < 4; ky++) {
                int off = pbase + ky * 15;
                float row[14];
                #pragma unroll
                for (int q = 0; q < 14; q++) row[q] = sin_[off + q];
                int kb = icl * 16 + ky * 4;
                #pragma unroll
                for (int kx = 0; kx < 4; kx++) {
                    float wv[8];
                    #pragma unroll
                    for (int m = 0; m < 8; m++) wv[m] = wrow0[m * 129 + kb + kx];
                    #pragma unroll
                    for (int m = 0; m < 8; m++)
                        #pragma unroll
                        for (int i = 0; i < 6; i++)
                            acc[m][i] += wv[m] * row[kx + 2 * i];
                }
            }
        }
    }
    int ib = ib4 * 4 + img_l;
    #pragma unroll
    for (int m = 0; m < 8; m++) {
        int oc = ocg * 8 + m;
        float bb = bias[oc];
        #pragma unroll
        for (int i = 0; i < 6; i++)
            g_c2o[(size_t)ib * 2304 + oc * 36 + oy * 6 + i] = fmaxf(acc[m][i] + bb, 0.f);
    }
}

// ================= conv3: (64,6,6) k3 s1 -> (64,4,4), relu ==================
// Register-tiled: thread computes 8 oc x 4 ox. 8 images/block, 256 threads.
__global__ __launch_bounds__(256) void k_conv3(const float* __restrict__ w,
                                               const float* __restrict__ bias) {
    extern __shared__ float sh[];
    float* sin_ = sh;            // 8*2304 = 18432
    float* swt  = sh + 18432;    // [64][145] = 9280
    int ib8 = blockIdx.x;        // 128 blocks
    int tid = threadIdx.x;
    for (int i = tid; i < 18432; i += 256)
        sin_[i] = g_c2o[(size_t)ib8 * 18432 + i];

    int ocg = tid & 7;           // 8 groups of 8 oc
    int ntile = tid >> 3;        // 0..31 = 8 img x 4 oy
    int img_l = ntile >> 2, oy = ntile & 3;
    int base_in = img_l * 2304 + oy * 6;

    float acc[8][4];
    #pragma unroll
    for (int m = 0; m < 8; m++)
        #pragma unroll
        for (int i = 0; i < 4; i++) acc[m][i] = 0.f;

    for (int cb = 0; cb < 4; cb++) {
        __syncthreads();
        for (int i = tid; i < 9216; i += 256) {
            int oc = i / 144, kk = i % 144;
            swt[oc * 145 + kk] = w[oc * 576 + cb * 144 + kk];
        }
        __syncthreads();
        const float* wrow0 = swt + (ocg * 8) * 145;
        #pragma unroll
        for (int icl = 0; icl < 16; icl++) {
            int pbase = base_in + (cb * 16 + icl) * 36;
            #pragma unroll
            for (int ky = 0; ky < 3; ky++) {
                int off = pbase + ky * 6;
                float row[6];
                #pragma unroll
                for (int q = 0; q < 6; q++) row[q] = sin_[off + q];
                int kb = icl * 9 + ky * 3;
                #pragma unroll
                for (int kx = 0; kx < 3; kx++) {
                    float wv[8];
                    #pragma unroll
                    for (int m = 0; m < 8; m++) wv[m] = wrow0[m * 145 + kb + kx];
                    #pragma unroll
                    for (int m = 0; m < 8; m++)
                        #pragma unroll
                        for (int i = 0; i < 4; i++)
                            acc[m][i] += wv[m] * row[kx + i];
                }
            }
        }
    }
    int ib = ib8 * 8 + img_l;
    #pragma unroll
    for (int m = 0; m < 8; m++) {
        int oc = ocg * 8 + m;
        float bb = bias[oc];
        #pragma unroll
        for (int i = 0; i < 4; i++)
            g_c3o[(size_t)ib * 1024 + oc * 16 + oy * 4 + i] = fmaxf(acc[m][i] + bb, 0.f);
    }
}

// ================= fc: SGEMM 1024x512x1024 -> g_h (+relu) ==================
// Block: 64 img x 64 oc tile, 256 threads, thread tile 4x4, K-chunk 32.
__global__ __launch_bounds__(256) void k_fc2(const float* __restrict__ bias) {
    __shared__ __align__(16) float Xs[64][33];   // [img][kk]
    __shared__ __align__(16) float Ws[32][64];   // [kk][oc]
    int i0 = blockIdx.x * 64;   // img
    int j0 = blockIdx.y * 64;   // oc
    int tid = threadIdx.x;
    int im_g = tid & 15, oc_g = tid >> 4;

    float acc[4][4];
    #pragma unroll
    for (int m = 0; m < 4; m++)
        #pragma unroll
        for (int n = 0; n < 4; n++) acc[m][n] = 0.f;

    for (int k0 = 0; k0 < 1024; k0 += 32) {
        __syncthreads();
        #pragma unroll
        for (int r = 0; r < 8; r++) {
            int i = tid + 256 * r;
            int im = i >> 5, kk = i & 31;
            Xs[im][kk] = g_c3o[(size_t)(i0 + im) * 1024 + k0 + kk];
        }
        #pragma unroll
        for (int r = 0; r < 8; r++) {
            int i = tid + 256 * r;
            int kk = i >> 6, oc = i & 63;
            Ws[kk][oc] = g_fcwt[(size_t)(k0 + kk) * 512 + j0 + oc];
        }
        __syncthreads();
        #pragma unroll
        for (int kk = 0; kk < 32; kk++) {
            float4 wv = *(const float4*)&Ws[kk][oc_g * 4];
            float xv[4];
            #pragma unroll
            for (int m = 0; m < 4; m++) xv[m] = Xs[im_g * 4 + m][kk];
            #pragma unroll
            for (int m = 0; m < 4; m++) {
                acc[m][0] += xv[m] * wv.x;
                acc[m][1] += xv[m] * wv.y;
                acc[m][2] += xv[m] * wv.z;
                acc[m][3] += xv[m] * wv.w;
            }
        }
    }
    #pragma unroll
    for (int n = 0; n < 4; n++) {
        int oc = j0 + oc_g * 4 + n;
        float bb = bias[oc];
        #pragma unroll
        for (int m = 0; m < 4; m++) {
            int img = i0 + im_g * 4 + m;
            g_h[(size_t)img * MAP + oc] = fmaxf(acc[m][n] + bb, 0.f);
        }
    }
}

// ---------------- onehot tail of g_h ----------------
__global__ void k_onehot(const int* __restrict__ lastact) {
    int i = blockIdx.x * 256 + threadIdx.x;
    if (i < TB * NACT) {
        int ib = i / NACT, a = i % NACT;
        g_h[(size_t)ib * MAP + 512 + a] = (lastact[ib] == a) ? 1.f : 0.f;
    }
}

// ---------------- zero acc0 ----------------
__global__ void k_zero() { g_acc0[blockIdx.x * 128 + threadIdx.x] = 0.f; }

// ---------------- acc0 = W_all @ state0_flat  (general correctness; zeros in bench) ------
__global__ __launch_bounds__(128) void k_acc0(const float* __restrict__ s0) {
    extern __shared__ float s0s[];  // 32 * 512 floats
    int f0 = blockIdx.x * 512;
    int j = threadIdx.x;
    for (int i = threadIdx.x; i < 32 * 512; i += 128) {
        int b = i >> 9; int fo = i & 511; int f = f0 + fo;
        s0s[i] = (f < FLAT) ? s0[(size_t)b * FLAT + f] : 0.f;
    }
    __syncthreads();
    float part[32];
    #pragma unroll
    for (int b = 0; b < 32; b++) part[b] = 0.f;
    int fmax = FLAT - f0; if (fmax > 512) fmax = 512;
    for (int fo = 0; fo < fmax; fo++) {
        float w = g_Wt[(size_t)(f0 + fo) * 128 + j];
        #pragma unroll
        for (int b = 0; b < 32; b++) part[b] += w * s0s[b * 512 + fo];
    }
    #pragma unroll
    for (int b = 0; b < 32; b++) atomicAdd(&g_acc0[b * 128 + j], part[b]);
}

// ---------------- sequential scan + incremental head GEMM ----------------
__global__ __launch_bounds__(512) void k_scan(const float* __restrict__ done,
                                              const int* __restrict__ pos,
                                              const float* __restrict__ s0,
                                              const float* __restrict__ pb1,
                                              const float* __restrict__ vb1,
                                              const float* __restrict__ pw2,
                                              const float* __restrict__ pb2,
                                              const float* __restrict__ vw2,
                                              const float* __restrict__ vb2,
                                              float* __restrict__ logits,
                                              float* __restrict__ vout) {
    __shared__ float delta[520];
    __shared__ float accs[128];
    __shared__ float th[128];
    __shared__ float partials[512];
    __shared__ int lastw[256];
    int b = blockIdx.x;
    int tid = threadIdx.x;
    int j = tid & 127, kq = tid >> 7;
    if (tid < 256) lastw[tid] = -2;
    if (tid < 128) accs[tid] = g_acc0[b * 128 + tid];
    for (int t = 0; t < T_; t++) {
        __syncthreads();
        float dn = done[t * B_ + b];
        if (dn != 0.0f) {
            if (tid < 128) accs[tid] = 0.f;
            if (tid < 256) lastw[tid] = -1;
        }
        __syncthreads();
        int r = t * B_ + b;
        int cell = pos[r * 2] * 16 + pos[r * 2 + 1];
        int code = lastw[cell];
        const float* hrow = g_h + (size_t)r * MAP;
        for (int k = tid; k < MAP; k += 512) {
            float old = 0.f;
            if (code >= 0)       old = g_h[(size_t)(code * B_ + b) * MAP + k];
            else if (code == -2) old = s0[(size_t)b * FLAT + k * 256 + cell];
            delta[k] = hrow[k] - old;
        }
        __syncthreads();
        float p = 0.f;
        const float* wtp = g_Wt + (size_t)cell * 128 + j;
        for (int k = kq; k < MAP; k += 4)
            p += wtp[(size_t)k * 32768] * delta[k];
        partials[tid] = p;
        __syncthreads();
        if (tid < 128) {
            float a = accs[tid] + partials[tid] + partials[tid + 128] +
                      partials[tid + 256] + partials[tid + 384];
            accs[tid] = a;
            float bb = (tid < 64) ? pb1[tid] : vb1[tid - 64];
            th[tid] = tanhf(a + bb);
        }
        __syncthreads();
        if (tid < NACT) {
            float s = pb2[tid];
            #pragma unroll
            for (int q = 0; q < 64; q++) s += th[q] * pw2[tid * 64 + q];
            logits[r * NACT + tid] = s;
        } else if (tid == 8) {
            float s = vb2[0];
            #pragma unroll
            for (int q = 0; q < 64; q++) s += th[64 + q] * vw2[q];
            vout[r] = s;
        } else if (tid == 16) {
            lastw[cell] = t;
        }
    }
    __syncthreads();
    if (tid < 256) g_lastw[b * 256 + tid] = lastw[tid];
}

// ---------------- reconstruct final_state ----------------
__global__ __launch_bounds__(256) void k_final(const float* __restrict__ s0,
                                               float* __restrict__ out) {
    int b = blockIdx.y;
    int f = blockIdx.x * 256 + threadIdx.x;
    int cell = f & 255, k = f >> 8;
    int code = g_lastw[b * 256 + cell];
    float v;
    if (code >= 0)       v = g_h[(size_t)(code * B_ + b) * MAP + k];
    else if (code == -2) v = s0[(size_t)b * FLAT + f];
    else                 v = 0.f;
    out[(size_t)b * FLAT + f] = v;
}

// ---------------- host ----------------
extern "C" void kernel_launch(void* const* d_in, const int* in_sizes, int n_in,
                              void* d_out, int out_size) {
    const float* image  = (const float*)d_in[0];
    const int*   lact   = (const int*)  d_in[1];
    const int*   pos    = (const int*)  d_in[2];
    const float* done   = (const float*)d_in[3];
    const float* state0 = (const float*)d_in[4];
    const float* c1w = (const float*)d_in[5];
    const float* c1b = (const float*)d_in[6];
    const float* c2w = (const float*)d_in[7];
    const float* c2b = (const float*)d_in[8];
    const float* c3w = (const float*)d_in[9];
    const float* c3b = (const float*)d_in[10];
    const float* fcw = (const float*)d_in[11];
    const float* fcb = (const float*)d_in[12];
    const float* pw1 = (const float*)d_in[13];
    const float* pb1 = (const float*)d_in[14];
    const float* pw2 = (const float*)d_in[15];
    const float* pb2 = (const float*)d_in[16];
    const float* vw1 = (const float*)d_in[17];
    const float* vb1 = (const float*)d_in[18];
    const float* vw2 = (const float*)d_in[19];
    const float* vb2 = (const float*)d_in[20];

    float* out_logits = (float*)d_out;                   // 1024*5
    float* out_v      = (float*)d_out + TB * NACT;       // 1024
    float* out_state  = (float*)d_out + TB * NACT + TB;  // 32*132352

    static int attr_done = 0;
    if (!attr_done) {
        cudaFuncSetAttribute(k_conv1, cudaFuncAttributeMaxDynamicSharedMemorySize, 73856);
        cudaFuncSetAttribute(k_conv2, cudaFuncAttributeMaxDynamicSharedMemorySize, 148224);
        cudaFuncSetAttribute(k_conv3, cudaFuncAttributeMaxDynamicSharedMemorySize, 110848);
        cudaFuncSetAttribute(k_acc0,  cudaFuncAttributeMaxDynamicSharedMemorySize, 68 * 1024);
        attr_done = 1;
    }

    // weight transposes (independent of data path)
    k_transW <<<dim3(FLAT / 32, 4), dim3(32, 32)>>>(pw1, vw1);
    k_transFC<<<dim3(32, 16),       dim3(32, 32)>>>(fcw);

    // CNN feature path (register-tiled)
    k_conv1<<<TB, 192, 73856>>>(image, c1w, c1b);
    k_conv2<<<TB / 4, 192, 148224>>>(c2w, c2b);
    k_conv3<<<TB / 8, 256, 110848>>>(c3w, c3b);
    k_fc2  <<<dim3(16, 8), 256>>>(fcb);
    k_onehot<<<(TB * NACT + 255) / 256, 256>>>(lact);

    // initial accumulator from state0 (general; zeros in this bench)
    k_zero <<<32, 128>>>();
    k_acc0 <<<(FLAT + 511) / 512, 128, 32 * 512 * 4>>>(state0);

    // sequential incremental scan producing logits & values
    k_scan <<<B_, 512>>>(done, pos, state0, pb1, vb1, pw2, pb2, vw2, vb2,
                         out_logits, out_v);

    // final state reconstruction
    k_final<<<dim3(FLAT / 256, B_), 256>>>(state0, out_state);

    (void)in_sizes; (void)n_in; (void)out_size;
}

// round 3
// speedup vs baseline: 2.0169x; 1.2346x over previous
#include <cuda_runtime.h>
#include <cuda_bf16.h>

#define T_ 32
#define B_ 32
#define TB 1024
#define MAP 517
#define FLAT 132352   // 517*256
#define NACT 5

// ---------------- scratch (device globals; no cudaMalloc allowed) ----------------
__device__ float g_Wt[FLAT * 128];      // [f][j]  j<64 pol rows, j>=64 val rows  (67.8MB)
__device__ float g_fcwt[1024 * 512];    // [k][j]
__device__ float g_c1o[TB * 32 * 225];  // conv1 out (TB,32,15,15)
__device__ float g_c2o[TB * 64 * 36];   // conv2 out (TB,64,6,6)
__device__ float g_c3o[TB * 1024];      // conv3 out flattened (TB,1024)
__device__ float g_h[TB * MAP];         // per-step feature+onehot (TB,517)
__device__ float g_acc0[B_ * 128];      // initial accumulator from state0
__device__ int   g_lastw[B_ * 256];     // last writer step per cell (-2 state0, -1 zero)

// ---------------- transpose big head weights: Wt[f*128+j] ----------------
__global__ void k_transW(const float* __restrict__ pol, const float* __restrict__ val) {
    __shared__ float tile[32][33];
    int f = blockIdx.x * 32 + threadIdx.x;
    int j = blockIdx.y * 32 + threadIdx.y;
    const float* src = (j < 64) ? (pol + (size_t)j * FLAT) : (val + (size_t)(j - 64) * FLAT);
    tile[threadIdx.y][threadIdx.x] = src[f];
    __syncthreads();
    int fo = blockIdx.x * 32 + threadIdx.y;
    int jo = blockIdx.y * 32 + threadIdx.x;
    g_Wt[(size_t)fo * 128 + jo] = tile[threadIdx.x][threadIdx.y];
}

// ---------------- transpose fc weights: fcwt[k*512+j] = fc_w[j*1024+k] ----------------
__global__ void k_transFC(const float* __restrict__ fcw) {
    __shared__ float tile[32][33];
    int k = blockIdx.x * 32 + threadIdx.x;
    int j = blockIdx.y * 32 + threadIdx.y;
    tile[threadIdx.y][threadIdx.x] = fcw[j * 1024 + k];
    __syncthreads();
    int ko = blockIdx.x * 32 + threadIdx.y;
    int jo = blockIdx.y * 32 + threadIdx.x;
    g_fcwt[ko * 512 + jo] = tile[threadIdx.x][threadIdx.y];
}

// ================= conv1: (3,64,64) k8 s4 -> (32,15,15), relu ==================
// thread tile: 4 oc x 5 ox. 384 threads (360 active), 1 image/block, 2 blocks/SM.
__global__ __launch_bounds__(384) void k_conv1(const float* __restrict__ img,
                                               const float* __restrict__ w,
                                               const float* __restrict__ bias) {
    extern __shared__ float sh[];
    float* simg = sh;                 // 12288
    float* swt  = sh + 12288;         // [32][193] = 6176
    int ib = blockIdx.x;
    int tid = threadIdx.x;
    const float* ip = img + (size_t)ib * 12288;
    for (int i = tid; i < 12288; i += 384) simg[i] = ip[i];
    for (int i = tid; i < 6144; i += 384) {
        int oc = i / 192, kk = i % 192;
        swt[oc * 193 + kk] = w[i];
    }
    __syncthreads();

    int ocg = tid & 7;          // 8 groups of 4 oc
    int ntile = tid >> 3;       // 0..47, active < 45
    bool active = (ntile < 45);
    int oy = ntile / 3, oxb = (ntile % 3) * 5;
    int ibase = active ? (oy * 256 + oxb * 4) : 0;

    float acc[4][5];
    #pragma unroll
    for (int m = 0; m < 4; m++)
        #pragma unroll
        for (int i = 0; i < 5; i++) acc[m][i] = 0.f;

    const float* wrow0 = swt + (ocg * 4) * 193;
    #pragma unroll
    for (int c = 0; c < 3; c++) {
        #pragma unroll
        for (int ky = 0; ky < 8; ky++) {
            int off = c * 4096 + ky * 64 + ibase;
            float row[24];
            #pragma unroll
            for (int q = 0; q < 24; q++) row[q] = simg[off + q];
            int kb = c * 64 + ky * 8;
            #pragma unroll
            for (int kx = 0; kx < 8; kx++) {
                float wv[4];
                #pragma unroll
                for (int m = 0; m < 4; m++) wv[m] = wrow0[m * 193 + kb + kx];
                #pragma unroll
                for (int m = 0; m < 4; m++)
                    #pragma unroll
                    for (int i = 0; i < 5; i++)
                        acc[m][i] += wv[m] * row[kx + 4 * i];
            }
        }
    }
    if (active) {
        #pragma unroll
        for (int m = 0; m < 4; m++) {
            int oc = ocg * 4 + m;
            float bb = bias[oc];
            #pragma unroll
            for (int i = 0; i < 5; i++)
                g_c1o[(size_t)ib * 7200 + oc * 225 + oy * 15 + oxb + i] =
                    fmaxf(acc[m][i] + bb, 0.f);
        }
    }
}

// ================= conv2: (32,15,15) k4 s2 -> (64,6,6), relu ==================
// thread tile: 4 oc x 6 ox. 4 images/block, 384 threads, ic-chunked smem (~60KB).
__global__ __launch_bounds__(384) void k_conv2(const float* __restrict__ w,
                                               const float* __restrict__ bias) {
    extern __shared__ float sh[];
    float* sin_ = sh;            // 4 img * 8 ic * 225 = 7200
    float* swt  = sh + 7200;     // [64][129] = 8256
    int ib4 = blockIdx.x;        // 256 blocks
    int tid = threadIdx.x;

    int ocg = tid & 15;          // 16 groups of 4 oc
    int ntile = tid >> 4;        // 0..23 = 4 img x 6 oy
    int img_l = ntile / 6, oy = ntile % 6;

    float acc[4][6];
    #pragma unroll
    for (int m = 0; m < 4; m++)
        #pragma unroll
        for (int i = 0; i < 6; i++) acc[m][i] = 0.f;

    for (int cb = 0; cb < 4; cb++) {
        __syncthreads();
        for (int i = tid; i < 7200; i += 384) {
            int img = i / 1800, rest = i % 1800;
            sin_[i] = g_c1o[(size_t)ib4 * 28800 + img * 7200 + cb * 1800 + rest];
        }
        for (int i = tid; i < 8192; i += 384) {
            int oc = i >> 7, kk = i & 127;
            swt[oc * 129 + kk] = w[oc * 512 + cb * 128 + kk];
        }
        __syncthreads();
        const float* wrow0 = swt + (ocg * 4) * 129;
        int base_in = img_l * 1800 + oy * 30;
        #pragma unroll
        for (int icl = 0; icl < 8; icl++) {
            int pbase = base_in + icl * 225;
            #pragma unroll
            for (int ky = 0; ky < 4; ky++) {
                int off = pbase + ky * 15;
                float row[14];
                #pragma unroll
                for (int q = 0; q < 14; q++) row[q] = sin_[off + q];
                int kb = icl * 16 + ky * 4;
                #pragma unroll
                for (int kx = 0; kx < 4; kx++) {
                    float wv[4];
                    #pragma unroll
                    for (int m = 0; m < 4; m++) wv[m] = wrow0[m * 129 + kb + kx];
                    #pragma unroll
                    for (int m = 0; m < 4; m++)
                        #pragma unroll
                        for (int i = 0; i < 6; i++)
                            acc[m][i] += wv[m] * row[kx + 2 * i];
                }
            }
        }
    }
    int ib = ib4 * 4 + img_l;
    #pragma unroll
    for (int m = 0; m < 4; m++) {
        int oc = ocg * 4 + m;
        float bb = bias[oc];
        #pragma unroll
        for (int i = 0; i < 6; i++)
            g_c2o[(size_t)ib * 2304 + oc * 36 + oy * 6 + i] = fmaxf(acc[m][i] + bb, 0.f);
    }
}

// ================= conv3: (64,6,6) k3 s1 -> (64,4,4), relu ==================
// thread tile: 4 oc x 4 ox. 4 images/block (grid 256), 256 threads, ic-chunked.
__global__ __launch_bounds__(256) void k_conv3(const float* __restrict__ w,
                                               const float* __restrict__ bias) {
    extern __shared__ float sh[];
    float* sin_ = sh;            // 4 img * 16 ic * 36 = 2304
    float* swt  = sh + 2304;     // [64][145] = 9280
    int ib4 = blockIdx.x;        // 256 blocks
    int tid = threadIdx.x;

    int ocg = tid & 15;          // 16 groups of 4 oc
    int ntile = tid >> 4;        // 0..15 = 4 img x 4 oy
    int img_l = ntile >> 2, oy = ntile & 3;

    float acc[4][4];
    #pragma unroll
    for (int m = 0; m < 4; m++)
        #pragma unroll
        for (int i = 0; i < 4; i++) acc[m][i] = 0.f;

    for (int cb = 0; cb < 4; cb++) {
        __syncthreads();
        for (int i = tid; i < 2304; i += 256) {
            int img = i / 576, rest = i % 576;
            sin_[i] = g_c2o[(size_t)ib4 * 9216 + img * 2304 + cb * 576 + rest];
        }
        for (int i = tid; i < 9216; i += 256) {
            int oc = i / 144, kk = i % 144;
            swt[oc * 145 + kk] = w[oc * 576 + cb * 144 + kk];
        }
        __syncthreads();
        const float* wrow0 = swt + (ocg * 4) * 145;
        int base_in = img_l * 576 + oy * 6;
        #pragma unroll
        for (int icl = 0; icl < 16; icl++) {
            int pbase = base_in + icl * 36;
            #pragma unroll
            for (int ky = 0; ky < 3; ky++) {
                int off = pbase + ky * 6;
                float row[6];
                #pragma unroll
                for (int q = 0; q < 6; q++) row[q] = sin_[off + q];
                int kb = icl * 9 + ky * 3;
                #pragma unroll
                for (int kx = 0; kx < 3; kx++) {
                    float wv[4];
                    #pragma unroll
                    for (int m = 0; m < 4; m++) wv[m] = wrow0[m * 145 + kb + kx];
                    #pragma unroll
                    for (int m = 0; m < 4; m++)
                        #pragma unroll
                        for (int i = 0; i < 4; i++)
                            acc[m][i] += wv[m] * row[kx + i];
                }
            }
        }
    }
    int ib = ib4 * 4 + img_l;
    #pragma unroll
    for (int m = 0; m < 4; m++) {
        int oc = ocg * 4 + m;
        float bb = bias[oc];
        #pragma unroll
        for (int i = 0; i < 4; i++)
            g_c3o[(size_t)ib * 1024 + oc * 16 + oy * 4 + i] = fmaxf(acc[m][i] + bb, 0.f);
    }
}

// ================= fc: SGEMM 1024x512x1024 -> g_h (+relu), float4 LDS ==========
__global__ __launch_bounds__(256) void k_fc2(const float* __restrict__ bias) {
    __shared__ __align__(16) float Xs[32][72];   // [kk][img]
    __shared__ __align__(16) float Ws[32][64];   // [kk][oc]
    int i0 = blockIdx.x * 64;   // img
    int j0 = blockIdx.y * 64;   // oc
    int tid = threadIdx.x;
    int im_g = tid & 15, oc_g = tid >> 4;

    float acc[4][4];
    #pragma unroll
    for (int m = 0; m < 4; m++)
        #pragma unroll
        for (int n = 0; n < 4; n++) acc[m][n] = 0.f;

    for (int k0 = 0; k0 < 1024; k0 += 32) {
        __syncthreads();
        #pragma unroll
        for (int r = 0; r < 8; r++) {
            int i = tid + 256 * r;
            int im = i >> 5, kk = i & 31;
            Xs[kk][im] = g_c3o[(size_t)(i0 + im) * 1024 + k0 + kk];
        }
        #pragma unroll
        for (int r = 0; r < 8; r++) {
            int i = tid + 256 * r;
            int kk = i >> 6, oc = i & 63;
            Ws[kk][oc] = g_fcwt[(size_t)(k0 + kk) * 512 + j0 + oc];
        }
        __syncthreads();
        #pragma unroll
        for (int kk = 0; kk < 32; kk++) {
            float4 wv = *(const float4*)&Ws[kk][oc_g * 4];
            float4 xv = *(const float4*)&Xs[kk][im_g * 4];
            acc[0][0] += xv.x * wv.x; acc[0][1] += xv.x * wv.y;
            acc[0][2] += xv.x * wv.z; acc[0][3] += xv.x * wv.w;
            acc[1][0] += xv.y * wv.x; acc[1][1] += xv.y * wv.y;
            acc[1][2] += xv.y * wv.z; acc[1][3] += xv.y * wv.w;
            acc[2][0] += xv.z * wv.x; acc[2][1] += xv.z * wv.y;
            acc[2][2] += xv.z * wv.z; acc[2][3] += xv.z * wv.w;
            acc[3][0] += xv.w * wv.x; acc[3][1] += xv.w * wv.y;
            acc[3][2] += xv.w * wv.z; acc[3][3] += xv.w * wv.w;
        }
    }
    #pragma unroll
    for (int n = 0; n < 4; n++) {
        int oc = j0 + oc_g * 4 + n;
        float bb = bias[oc];
        #pragma unroll
        for (int m = 0; m < 4; m++) {
            int img = i0 + im_g * 4 + m;
            g_h[(size_t)img * MAP + oc] = fmaxf(acc[m][n] + bb, 0.f);
        }
    }
}

// ---------------- onehot tail of g_h ----------------
__global__ void k_onehot(const int* __restrict__ lastact) {
    int i = blockIdx.x * 256 + threadIdx.x;
    if (i < TB * NACT) {
        int ib = i / NACT, a = i % NACT;
        g_h[(size_t)ib * MAP + 512 + a] = (lastact[ib] == a) ? 1.f : 0.f;
    }
}

// ---------------- zero acc0 ----------------
__global__ void k_zero() { g_acc0[blockIdx.x * 128 + threadIdx.x] = 0.f; }

// ======== acc0[j][b] = sum_f W[j][f]*s0[b][f]; tiled GEMM, split-K, atomics ======
// Reads pol/val directly (no transW dependency). grid 517 (K chunks of 256), 256 thr.
__global__ __launch_bounds__(256) void k_acc0(const float* __restrict__ pol,
                                              const float* __restrict__ val,
                                              const float* __restrict__ s0) {
    __shared__ __align__(16) float Wt2[64][132];  // [kk][j]
    __shared__ __align__(16) float Ss[64][36];    // [kk][b]
    int kb0 = blockIdx.x * 256;
    int tid = threadIdx.x;
    int jg = tid >> 3;   // 0..31 -> j tile of 4
    int bg = tid & 7;    // 0..7  -> b tile of 4

    float acc[4][4];
    #pragma unroll
    for (int m = 0; m < 4; m++)
        #pragma unroll
        for (int n = 0; n < 4; n++) acc[m][n] = 0.f;

    for (int sub = 0; sub < 4; sub++) {
        int kbase = kb0 + sub * 64;
        __syncthreads();
        for (int i = tid; i < 8192; i += 256) {
            int kk = i & 63, j = i >> 6;
            const float* src = (j < 64) ? (pol + (size_t)j * FLAT)
                                        : (val + (size_t)(j - 64) * FLAT);
            Wt2[kk][j] = src[kbase + kk];
        }
        for (int i = tid; i < 2048; i += 256) {
            int kk = i & 63, b = i >> 6;
            Ss[kk][b] = s0[(size_t)b * FLAT + kbase + kk];
        }
        __syncthreads();
        #pragma unroll
        for (int kk = 0; kk < 64; kk++) {
            float4 wv = *(const float4*)&Wt2[kk][jg * 4];
            float4 sv = *(const float4*)&Ss[kk][bg * 4];
            acc[0][0] += wv.x * sv.x; acc[0][1] += wv.x * sv.y;
            acc[0][2] += wv.x * sv.z; acc[0][3] += wv.x * sv.w;
            acc[1][0] += wv.y * sv.x; acc[1][1] += wv.y * sv.y;
            acc[1][2] += wv.y * sv.z; acc[1][3] += wv.y * sv.w;
            acc[2][0] += wv.z * sv.x; acc[2][1] += wv.z * sv.y;
            acc[2][2] += wv.z * sv.z; acc[2][3] += wv.z * sv.w;
            acc[3][0] += wv.w * sv.x; acc[3][1] += wv.w * sv.y;
            acc[3][2] += wv.w * sv.z; acc[3][3] += wv.w * sv.w;
        }
    }
    #pragma unroll
    for (int m = 0; m < 4; m++)
        #pragma unroll
        for (int n = 0; n < 4; n++)
            atomicAdd(&g_acc0[(bg * 4 + n) * 128 + jg * 4 + m], acc[m][n]);
}

// ---------------- sequential scan + incremental head GEMM ----------------
__global__ __launch_bounds__(512) void k_scan(const float* __restrict__ done,
                                              const int* __restrict__ pos,
                                              const float* __restrict__ s0,
                                              const float* __restrict__ pb1,
                                              const float* __restrict__ vb1,
                                              const float* __restrict__ pw2,
                                              const float* __restrict__ pb2,
                                              const float* __restrict__ vw2,
                                              const float* __restrict__ vb2,
                                              float* __restrict__ logits,
                                              float* __restrict__ vout) {
    __shared__ float delta[520];
    __shared__ float accs[128];
    __shared__ float th[128];
    __shared__ float partials[512];
    __shared__ int lastw[256];
    int b = blockIdx.x;
    int tid = threadIdx.x;
    int j = tid & 127, kq = tid >> 7;
    if (tid < 256) lastw[tid] = -2;
    if (tid < 128) accs[tid] = g_acc0[b * 128 + tid];
    for (int t = 0; t < T_; t++) {
        __syncthreads();
        float dn = done[t * B_ + b];
        if (dn != 0.0f) {
            if (tid < 128) accs[tid] = 0.f;
            if (tid < 256) lastw[tid] = -1;
        }
        __syncthreads();
        int r = t * B_ + b;
        int cell = pos[r * 2] * 16 + pos[r * 2 + 1];
        int code = lastw[cell];
        const float* hrow = g_h + (size_t)r * MAP;
        for (int k = tid; k < MAP; k += 512) {
            float old = 0.f;
            if (code >= 0)       old = g_h[(size_t)(code * B_ + b) * MAP + k];
            else if (code == -2) old = s0[(size_t)b * FLAT + k * 256 + cell];
            delta[k] = hrow[k] - old;
        }
        __syncthreads();
        float p = 0.f;
        const float* wtp = g_Wt + (size_t)cell * 128 + j;
        for (int k = kq; k < MAP; k += 4)
            p += wtp[(size_t)k * 32768] * delta[k];
        partials[tid] = p;
        __syncthreads();
        if (tid < 128) {
            float a = accs[tid] + partials[tid] + partials[tid + 128] +
                      partials[tid + 256] + partials[tid + 384];
            accs[tid] = a;
            float bb = (tid < 64) ? pb1[tid] : vb1[tid - 64];
            th[tid] = tanhf(a + bb);
        }
        __syncthreads();
        if (tid < NACT) {
            float s = pb2[tid];
            #pragma unroll
            for (int q = 0; q < 64; q++) s += th[q] * pw2[tid * 64 + q];
            logits[r * NACT + tid] = s;
        } else if (tid == 8) {
            float s = vb2[0];
            #pragma unroll
            for (int q = 0; q < 64; q++) s += th[64 + q] * vw2[q];
            vout[r] = s;
        } else if (tid == 16) {
            lastw[cell] = t;
        }
    }
    __syncthreads();
    if (tid < 256) g_lastw[b * 256 + tid] = lastw[tid];
}

// ---------------- reconstruct final_state ----------------
__global__ __launch_bounds__(256) void k_final(const float* __restrict__ s0,
                                               float* __restrict__ out) {
    int b = blockIdx.y;
    int f = blockIdx.x * 256 + threadIdx.x;
    int cell = f & 255, k = f >> 8;
    int code = g_lastw[b * 256 + cell];
    float v;
    if (code >= 0)       v = g_h[(size_t)(code * B_ + b) * MAP + k];
    else if (code == -2) v = s0[(size_t)b * FLAT + f];
    else                 v = 0.f;
    out[(size_t)b * FLAT + f] = v;
}

// ---------------- host ----------------
extern "C" void kernel_launch(void* const* d_in, const int* in_sizes, int n_in,
                              void* d_out, int out_size) {
    const float* image  = (const float*)d_in[0];
    const int*   lact   = (const int*)  d_in[1];
    const int*   pos    = (const int*)  d_in[2];
    const float* done   = (const float*)d_in[3];
    const float* state0 = (const float*)d_in[4];
    const float* c1w = (const float*)d_in[5];
    const float* c1b = (const float*)d_in[6];
    const float* c2w = (const float*)d_in[7];
    const float* c2b = (const float*)d_in[8];
    const float* c3w = (const float*)d_in[9];
    const float* c3b = (const float*)d_in[10];
    const float* fcw = (const float*)d_in[11];
    const float* fcb = (const float*)d_in[12];
    const float* pw1 = (const float*)d_in[13];
    const float* pb1 = (const float*)d_in[14];
    const float* pw2 = (const float*)d_in[15];
    const float* pb2 = (const float*)d_in[16];
    const float* vw1 = (const float*)d_in[17];
    const float* vb1 = (const float*)d_in[18];
    const float* vw2 = (const float*)d_in[19];
    const float* vb2 = (const float*)d_in[20];

    float* out_logits = (float*)d_out;                   // 1024*5
    float* out_v      = (float*)d_out + TB * NACT;       // 1024
    float* out_state  = (float*)d_out + TB * NACT + TB;  // 32*132352

    static int attr_done = 0;
    if (!attr_done) {
        cudaFuncSetAttribute(k_conv1, cudaFuncAttributeMaxDynamicSharedMemorySize, 73856);
        cudaFuncSetAttribute(k_conv2, cudaFuncAttributeMaxDynamicSharedMemorySize, 61824);
        cudaFuncSetAttribute(k_conv3, cudaFuncAttributeMaxDynamicSharedMemorySize, 46336);
        attr_done = 1;
    }

    // initial accumulator from state0 (independent of conv path / transW)
    k_zero <<<32, 128>>>();
    k_acc0 <<<517, 256>>>(pw1, vw1, state0);

    // weight transposes
    k_transFC<<<dim3(32, 16), dim3(32, 32)>>>(fcw);
    k_transW <<<dim3(FLAT / 32, 4), dim3(32, 32)>>>(pw1, vw1);

    // CNN feature path (register-tiled, occupancy-tuned)
    k_conv1<<<TB, 384, 73856>>>(image, c1w, c1b);
    k_conv2<<<TB / 4, 384, 61824>>>(c2w, c2b);
    k_conv3<<<TB / 4, 256, 46336>>>(c3w, c3b);
    k_fc2  <<<dim3(16, 8), 256>>>(fcb);
    k_onehot<<<(TB * NACT + 255) / 256, 256>>>(lact);

    // sequential incremental scan producing logits & values
    k_scan <<<B_, 512>>>(done, pos, state0, pb1, vb1, pw2, pb2, vw2, vb2,
                         out_logits, out_v);

    // final state reconstruction
    k_final<<<dim3(FLAT / 256, B_), 256>>>(state0, out_state);

    (void)in_sizes; (void)n_in; (void)out_size;
}

// round 4
// speedup vs baseline: 3.7433x; 1.8560x over previous
#include <cuda_runtime.h>
#include <cuda_bf16.h>

#define T_ 32
#define B_ 32
#define TB 1024
#define MAP 517
#define FLAT 132352   // 517*256
#define NACT 5
#define WCELL 66176   // 517*128 floats per cell

// ---------------- scratch (device globals; no cudaMalloc allowed) ----------------
__device__ float g_Wt[FLAT * 128];      // [cell][k][j] : cell*66176 + k*128 + j
__device__ float g_fcwt[1024 * 512];    // [k][j]
__device__ float g_c1o[TB * 32 * 225];  // conv1 out
__device__ float g_c2o[TB * 64 * 36];   // conv2 out
__device__ float g_c3o[TB * 1024];      // conv3 out flattened
__device__ float g_h[TB * MAP];         // per-step feature+onehot
__device__ float g_acc0[B_ * 128];      // initial accumulator from state0
__device__ int   g_lastw[B_ * 256];     // last writer step per cell (-2 state0, -1 zero)
__device__ int   g_cell[TB];            // cell index per (t,b)
__device__ int   g_code[TB];            // last-writer code per (t,b)
__device__ float g_c[TB * 128];         // per-step head contributions

// ======== transpose big head weights into [cell][k][j], float4 both sides ========
__global__ __launch_bounds__(256) void k_transW2(const float* __restrict__ pol,
                                                 const float* __restrict__ val) {
    __shared__ float tile[32][132];   // [f_local][j], row stride 132 (16B aligned)
    int f0 = blockIdx.x * 32;
    int tid = threadIdx.x;
    // read: 128 j rows x 32 f (8 float4 per row)
    #pragma unroll
    for (int rep = 0; rep < 4; rep++) {
        int idx = tid + rep * 256;        // 0..1023
        int j = idx >> 3, f4 = idx & 7;
        const float* src = (j < 64) ? (pol + (size_t)j * FLAT)
                                    : (val + (size_t)(j - 64) * FLAT);
        float4 v = *(const float4*)(src + f0 + f4 * 4);
        tile[f4 * 4 + 0][j] = v.x;
        tile[f4 * 4 + 1][j] = v.y;
        tile[f4 * 4 + 2][j] = v.z;
        tile[f4 * 4 + 3][j] = v.w;
    }
    __syncthreads();
    // write: per f row, 128 j as 32 float4 (contiguous 512B per (cell,k))
    #pragma unroll
    for (int rep = 0; rep < 4; rep++) {
        int idx = tid + rep * 256;
        int fr = idx >> 5, jg = idx & 31;
        int f = f0 + fr;
        int cell = f & 255, k = f >> 8;
        float4 w = *(const float4*)&tile[fr][jg * 4];
        *(float4*)(g_Wt + (size_t)cell * WCELL + k * 128 + jg * 4) = w;
    }
}

// ---------------- transpose fc weights: fcwt[k*512+j] = fc_w[j*1024+k] ----------------
__global__ void k_transFC(const float* __restrict__ fcw) {
    __shared__ float tile[32][33];
    int k = blockIdx.x * 32 + threadIdx.x;
    int j = blockIdx.y * 32 + threadIdx.y;
    tile[threadIdx.y][threadIdx.x] = fcw[j * 1024 + k];
    __syncthreads();
    int ko = blockIdx.x * 32 + threadIdx.y;
    int jo = blockIdx.y * 32 + threadIdx.x;
    g_fcwt[ko * 512 + jo] = tile[threadIdx.x][threadIdx.y];
}

// ================= conv1: (3,64,64) k8 s4 -> (32,15,15), relu ==================
__global__ __launch_bounds__(384) void k_conv1(const float* __restrict__ img,
                                               const float* __restrict__ w,
                                               const float* __restrict__ bias) {
    extern __shared__ float sh[];
    float* simg = sh;                 // 12288
    float* swt  = sh + 12288;         // [32][193]
    int ib = blockIdx.x;
    int tid = threadIdx.x;
    const float* ip = img + (size_t)ib * 12288;
    for (int i = tid; i < 12288; i += 384) simg[i] = ip[i];
    for (int i = tid; i < 6144; i += 384) {
        int oc = i / 192, kk = i % 192;
        swt[oc * 193 + kk] = w[i];
    }
    __syncthreads();

    int ocg = tid & 7;
    int ntile = tid >> 3;
    bool active = (ntile < 45);
    int oy = ntile / 3, oxb = (ntile % 3) * 5;
    int ibase = active ? (oy * 256 + oxb * 4) : 0;

    float acc[4][5];
    #pragma unroll
    for (int m = 0; m < 4; m++)
        #pragma unroll
        for (int i = 0; i < 5; i++) acc[m][i] = 0.f;

    const float* wrow0 = swt + (ocg * 4) * 193;
    #pragma unroll
    for (int c = 0; c < 3; c++) {
        #pragma unroll
        for (int ky = 0; ky < 8; ky++) {
            int off = c * 4096 + ky * 64 + ibase;
            float row[24];
            #pragma unroll
            for (int q = 0; q < 24; q++) row[q] = simg[off + q];
            int kb = c * 64 + ky * 8;
            #pragma unroll
            for (int kx = 0; kx < 8; kx++) {
                float wv[4];
                #pragma unroll
                for (int m = 0; m < 4; m++) wv[m] = wrow0[m * 193 + kb + kx];
                #pragma unroll
                for (int m = 0; m < 4; m++)
                    #pragma unroll
                    for (int i = 0; i < 5; i++)
                        acc[m][i] += wv[m] * row[kx + 4 * i];
            }
        }
    }
    if (active) {
        #pragma unroll
        for (int m = 0; m < 4; m++) {
            int oc = ocg * 4 + m;
            float bb = bias[oc];
            #pragma unroll
            for (int i = 0; i < 5; i++)
                g_c1o[(size_t)ib * 7200 + oc * 225 + oy * 15 + oxb + i] =
                    fmaxf(acc[m][i] + bb, 0.f);
        }
    }
}

// ================= conv2: (32,15,15) k4 s2 -> (64,6,6), relu ==================
__global__ __launch_bounds__(384) void k_conv2(const float* __restrict__ w,
                                               const float* __restrict__ bias) {
    extern __shared__ float sh[];
    float* sin_ = sh;            // 7200
    float* swt  = sh + 7200;     // [64][129]
    int ib4 = blockIdx.x;
    int tid = threadIdx.x;

    int ocg = tid & 15;
    int ntile = tid >> 4;
    int img_l = ntile / 6, oy = ntile % 6;

    float acc[4][6];
    #pragma unroll
    for (int m = 0; m < 4; m++)
        #pragma unroll
        for (int i = 0; i < 6; i++) acc[m][i] = 0.f;

    for (int cb = 0; cb < 4; cb++) {
        __syncthreads();
        for (int i = tid; i < 7200; i += 384) {
            int img = i / 1800, rest = i % 1800;
            sin_[i] = g_c1o[(size_t)ib4 * 28800 + img * 7200 + cb * 1800 + rest];
        }
        for (int i = tid; i < 8192; i += 384) {
            int oc = i >> 7, kk = i & 127;
            swt[oc * 129 + kk] = w[oc * 512 + cb * 128 + kk];
        }
        __syncthreads();
        const float* wrow0 = swt + (ocg * 4) * 129;
        int base_in = img_l * 1800 + oy * 30;
        #pragma unroll
        for (int icl = 0; icl < 8; icl++) {
            int pbase = base_in + icl * 225;
            #pragma unroll
            for (int ky = 0; ky < 4; ky++) {
                int off = pbase + ky * 15;
                float row[14];
                #pragma unroll
                for (int q = 0; q < 14; q++) row[q] = sin_[off + q];
                int kb = icl * 16 + ky * 4;
                #pragma unroll
                for (int kx = 0; kx < 4; kx++) {
                    float wv[4];
                    #pragma unroll
                    for (int m = 0; m < 4; m++) wv[m] = wrow0[m * 129 + kb + kx];
                    #pragma unroll
                    for (int m = 0; m < 4; m++)
                        #pragma unroll
                        for (int i = 0; i < 6; i++)
                            acc[m][i] += wv[m] * row[kx + 2 * i];
                }
            }
        }
    }
    int ib = ib4 * 4 + img_l;
    #pragma unroll
    for (int m = 0; m < 4; m++) {
        int oc = ocg * 4 + m;
        float bb = bias[oc];
        #pragma unroll
        for (int i = 0; i < 6; i++)
            g_c2o[(size_t)ib * 2304 + oc * 36 + oy * 6 + i] = fmaxf(acc[m][i] + bb, 0.f);
    }
}

// ================= conv3: (64,6,6) k3 s1 -> (64,4,4), relu ==================
__global__ __launch_bounds__(256) void k_conv3(const float* __restrict__ w,
                                               const float* __restrict__ bias) {
    extern __shared__ float sh[];
    float* sin_ = sh;            // 2304
    float* swt  = sh + 2304;     // [64][145]
    int ib4 = blockIdx.x;
    int tid = threadIdx.x;

    int ocg = tid & 15;
    int ntile = tid >> 4;
    int img_l = ntile >> 2, oy = ntile & 3;

    float acc[4][4];
    #pragma unroll
    for (int m = 0; m < 4; m++)
        #pragma unroll
        for (int i = 0; i < 4; i++) acc[m][i] = 0.f;

    for (int cb = 0; cb < 4; cb++) {
        __syncthreads();
        for (int i = tid; i < 2304; i += 256) {
            int img = i / 576, rest = i % 576;
            sin_[i] = g_c2o[(size_t)ib4 * 9216 + img * 2304 + cb * 576 + rest];
        }
        for (int i = tid; i < 9216; i += 256) {
            int oc = i / 144, kk = i % 144;
            swt[oc * 145 + kk] = w[oc * 576 + cb * 144 + kk];
        }
        __syncthreads();
        const float* wrow0 = swt + (ocg * 4) * 145;
        int base_in = img_l * 576 + oy * 6;
        #pragma unroll
        for (int icl = 0; icl < 16; icl++) {
            int pbase = base_in + icl * 36;
            #pragma unroll
            for (int ky = 0; ky < 3; ky++) {
                int off = pbase + ky * 6;
                float row[6];
                #pragma unroll
                for (int q = 0; q < 6; q++) row[q] = sin_[off + q];
                int kb = icl * 9 + ky * 3;
                #pragma unroll
                for (int kx = 0; kx < 3; kx++) {
                    float wv[4];
                    #pragma unroll
                    for (int m = 0; m < 4; m++) wv[m] = wrow0[m * 145 + kb + kx];
                    #pragma unroll
                    for (int m = 0; m < 4; m++)
                        #pragma unroll
                        for (int i = 0; i < 4; i++)
                            acc[m][i] += wv[m] * row[kx + i];
                }
            }
        }
    }
    int ib = ib4 * 4 + img_l;
    #pragma unroll
    for (int m = 0; m < 4; m++) {
        int oc = ocg * 4 + m;
        float bb = bias[oc];
        #pragma unroll
        for (int i = 0; i < 4; i++)
            g_c3o[(size_t)ib * 1024 + oc * 16 + oy * 4 + i] = fmaxf(acc[m][i] + bb, 0.f);
    }
}

// ================= fc: SGEMM 1024x512x1024 -> g_h (+relu), float4 LDS ==========
__global__ __launch_bounds__(256) void k_fc2(const float* __restrict__ bias) {
    __shared__ __align__(16) float Xs[32][72];   // [kk][img]
    __shared__ __align__(16) float Ws[32][64];   // [kk][oc]
    int i0 = blockIdx.x * 64;
    int j0 = blockIdx.y * 64;
    int tid = threadIdx.x;
    int im_g = tid & 15, oc_g = tid >> 4;

    float acc[4][4];
    #pragma unroll
    for (int m = 0; m < 4; m++)
        #pragma unroll
        for (int n = 0; n < 4; n++) acc[m][n] = 0.f;

    for (int k0 = 0; k0 < 1024; k0 += 32) {
        __syncthreads();
        #pragma unroll
        for (int r = 0; r < 8; r++) {
            int i = tid + 256 * r;
            int im = i >> 5, kk = i & 31;
            Xs[kk][im] = g_c3o[(size_t)(i0 + im) * 1024 + k0 + kk];
        }
        #pragma unroll
        for (int r = 0; r < 8; r++) {
            int i = tid + 256 * r;
            int kk = i >> 6, oc = i & 63;
            Ws[kk][oc] = g_fcwt[(size_t)(k0 + kk) * 512 + j0 + oc];
        }
        __syncthreads();
        #pragma unroll
        for (int kk = 0; kk < 32; kk++) {
            float4 wv = *(const float4*)&Ws[kk][oc_g * 4];
            float4 xv = *(const float4*)&Xs[kk][im_g * 4];
            acc[0][0] += xv.x * wv.x; acc[0][1] += xv.x * wv.y;
            acc[0][2] += xv.x * wv.z; acc[0][3] += xv.x * wv.w;
            acc[1][0] += xv.y * wv.x; acc[1][1] += xv.y * wv.y;
            acc[1][2] += xv.y * wv.z; acc[1][3] += xv.y * wv.w;
            acc[2][0] += xv.z * wv.x; acc[2][1] += xv.z * wv.y;
            acc[2][2] += xv.z * wv.z; acc[2][3] += xv.z * wv.w;
            acc[3][0] += xv.w * wv.x; acc[3][1] += xv.w * wv.y;
            acc[3][2] += xv.w * wv.z; acc[3][3] += xv.w * wv.w;
        }
    }
    #pragma unroll
    for (int n = 0; n < 4; n++) {
        int oc = j0 + oc_g * 4 + n;
        float bb = bias[oc];
        #pragma unroll
        for (int m = 0; m < 4; m++) {
            int img = i0 + im_g * 4 + m;
            g_h[(size_t)img * MAP + oc] = fmaxf(acc[m][n] + bb, 0.f);
        }
    }
}

// ---------------- onehot tail of g_h ----------------
__global__ void k_onehot(const int* __restrict__ lastact) {
    int i = blockIdx.x * 256 + threadIdx.x;
    if (i < TB * NACT) {
        int ib = i / NACT, a = i % NACT;
        g_h[(size_t)ib * MAP + 512 + a] = (lastact[ib] == a) ? 1.f : 0.f;
    }
}

// ---------------- zero acc0 ----------------
__global__ void k_zero() { g_acc0[blockIdx.x * 128 + threadIdx.x] = 0.f; }

// ======== acc0[j][b] = sum_f W[j][f]*s0[b][f]; tiled GEMM, split-K, atomics ======
__global__ __launch_bounds__(256) void k_acc0(const float* __restrict__ pol,
                                              const float* __restrict__ val,
                                              const float* __restrict__ s0) {
    __shared__ __align__(16) float Wt2[64][132];
    __shared__ __align__(16) float Ss[64][36];
    int kb0 = blockIdx.x * 256;
    int tid = threadIdx.x;
    int jg = tid >> 3;
    int bg = tid & 7;

    float acc[4][4];
    #pragma unroll
    for (int m = 0; m < 4; m++)
        #pragma unroll
        for (int n = 0; n < 4; n++) acc[m][n] = 0.f;

    for (int sub = 0; sub < 4; sub++) {
        int kbase = kb0 + sub * 64;
        __syncthreads();
        for (int i = tid; i < 8192; i += 256) {
            int kk = i & 63, j = i >> 6;
            const float* src = (j < 64) ? (pol + (size_t)j * FLAT)
                                        : (val + (size_t)(j - 64) * FLAT);
            Wt2[kk][j] = src[kbase + kk];
        }
        for (int i = tid; i < 2048; i += 256) {
            int kk = i & 63, b = i >> 6;
            Ss[kk][b] = s0[(size_t)b * FLAT + kbase + kk];
        }
        __syncthreads();
        #pragma unroll
        for (int kk = 0; kk < 64; kk++) {
            float4 wv = *(const float4*)&Wt2[kk][jg * 4];
            float4 sv = *(const float4*)&Ss[kk][bg * 4];
            acc[0][0] += wv.x * sv.x; acc[0][1] += wv.x * sv.y;
            acc[0][2] += wv.x * sv.z; acc[0][3] += wv.x * sv.w;
            acc[1][0] += wv.y * sv.x; acc[1][1] += wv.y * sv.y;
            acc[1][2] += wv.y * sv.z; acc[1][3] += wv.y * sv.w;
            acc[2][0] += wv.z * sv.x; acc[2][1] += wv.z * sv.y;
            acc[2][2] += wv.z * sv.z; acc[2][3] += wv.z * sv.w;
            acc[3][0] += wv.w * sv.x; acc[3][1] += wv.w * sv.y;
            acc[3][2] += wv.w * sv.z; acc[3][3] += wv.w * sv.w;
        }
    }
    #pragma unroll
    for (int m = 0; m < 4; m++)
        #pragma unroll
        for (int n = 0; n < 4; n++)
            atomicAdd(&g_acc0[(bg * 4 + n) * 128 + jg * 4 + m], acc[m][n]);
}

// ======== pass 1: integer last-writer scan (cheap, sequential in t only) ========
__global__ __launch_bounds__(32) void k_codes(const int* __restrict__ pos,
                                              const float* __restrict__ done) {
    __shared__ int lw[B_ * 256];
    int b = threadIdx.x;
    for (int c = 0; c < 256; c++) lw[b * 256 + c] = -2;
    for (int t = 0; t < T_; t++) {
        if (done[t * B_ + b] != 0.0f)
            for (int c = 0; c < 256; c++) lw[b * 256 + c] = -1;
        int r = t * B_ + b;
        int cell = pos[r * 2] * 16 + pos[r * 2 + 1];
        g_cell[r] = cell;
        g_code[r] = lw[b * 256 + cell];
        lw[b * 256 + cell] = t;
    }
    for (int c = 0; c < 256; c++) g_lastw[b * 256 + c] = lw[b * 256 + c];
}

// ======== pass 2: parallel per-(t,b) contribution dot products ========
// c[r][j] = W_cell[:,j] . (h_r - old_r)   -- 1024 independent blocks
__global__ __launch_bounds__(256) void k_dots(const float* __restrict__ s0) {
    __shared__ float delta[520];
    __shared__ float psum[8 * 128];
    int r = blockIdx.x;
    int b = r & 31;
    int tid = threadIdx.x;
    int cell = g_cell[r];
    int code = g_code[r];
    const float* hrow = g_h + (size_t)r * MAP;
    for (int k = tid; k < MAP; k += 256) {
        float old = 0.f;
        if (code >= 0)       old = g_h[(size_t)(code * B_ + b) * MAP + k];
        else if (code == -2) old = s0[(size_t)b * FLAT + k * 256 + cell];
        delta[k] = hrow[k] - old;
    }
    __syncthreads();
    int j4 = tid & 31;        // j group of 4
    int kq = tid >> 5;        // 0..7 k-split
    const float* wb = g_Wt + (size_t)cell * WCELL + j4 * 4;
    float4 a = make_float4(0.f, 0.f, 0.f, 0.f);
    for (int k = kq; k < MAP; k += 8) {
        float4 w = *(const float4*)(wb + k * 128);
        float d = delta[k];
        a.x += w.x * d; a.y += w.y * d; a.z += w.z * d; a.w += w.w * d;
    }
    psum[kq * 128 + j4 * 4 + 0] = a.x;
    psum[kq * 128 + j4 * 4 + 1] = a.y;
    psum[kq * 128 + j4 * 4 + 2] = a.z;
    psum[kq * 128 + j4 * 4 + 3] = a.w;
    __syncthreads();
    if (tid < 128) {
        float s = 0.f;
        #pragma unroll
        for (int q = 0; q < 8; q++) s += psum[q * 128 + tid];
        g_c[(size_t)r * 128 + tid] = s;
    }
}

// ======== pass 3: prefix accumulate + tanh + head GEMVs ========
__global__ __launch_bounds__(128) void k_scanfin(const float* __restrict__ done,
                                                 const float* __restrict__ pb1,
                                                 const float* __restrict__ vb1,
                                                 const float* __restrict__ pw2,
                                                 const float* __restrict__ pb2,
                                                 const float* __restrict__ vw2,
                                                 const float* __restrict__ vb2,
                                                 float* __restrict__ logits,
                                                 float* __restrict__ vout) {
    __shared__ float th[128];
    int b = blockIdx.x;
    int tid = threadIdx.x;
    float accv = g_acc0[b * 128 + tid];
    float bb = (tid < 64) ? pb1[tid] : vb1[tid - 64];
    for (int t = 0; t < T_; t++) {
        int r = t * B_ + b;
        float dn = done[r];
        if (dn != 0.0f) accv = 0.f;
        accv += g_c[(size_t)r * 128 + tid];
        th[tid] = tanhf(accv + bb);
        __syncthreads();
        if (tid < NACT) {
            float s = pb2[tid];
            #pragma unroll
            for (int q = 0; q < 64; q++) s += th[q] * pw2[tid * 64 + q];
            logits[r * NACT + tid] = s;
        } else if (tid == 8) {
            float s = vb2[0];
            #pragma unroll
            for (int q = 0; q < 64; q++) s += th[64 + q] * vw2[q];
            vout[r] = s;
        }
        __syncthreads();
    }
}

// ---------------- reconstruct final_state ----------------
__global__ __launch_bounds__(256) void k_final(const float* __restrict__ s0,
                                               float* __restrict__ out) {
    int b = blockIdx.y;
    int f = blockIdx.x * 256 + threadIdx.x;
    int cell = f & 255, k = f >> 8;
    int code = g_lastw[b * 256 + cell];
    float v;
    if (code >= 0)       v = g_h[(size_t)(code * B_ + b) * MAP + k];
    else if (code == -2) v = s0[(size_t)b * FLAT + f];
    else                 v = 0.f;
    out[(size_t)b * FLAT + f] = v;
}

// ---------------- host ----------------
extern "C" void kernel_launch(void* const* d_in, const int* in_sizes, int n_in,
                              void* d_out, int out_size) {
    const float* image  = (const float*)d_in[0];
    const int*   lact   = (const int*)  d_in[1];
    const int*   pos    = (const int*)  d_in[2];
    const float* done   = (const float*)d_in[3];
    const float* state0 = (const float*)d_in[4];
    const float* c1w = (const float*)d_in[5];
    const float* c1b = (const float*)d_in[6];
    const float* c2w = (const float*)d_in[7];
    const float* c2b = (const float*)d_in[8];
    const float* c3w = (const float*)d_in[9];
    const float* c3b = (const float*)d_in[10];
    const float* fcw = (const float*)d_in[11];
    const float* fcb = (const float*)d_in[12];
    const float* pw1 = (const float*)d_in[13];
    const float* pb1 = (const float*)d_in[14];
    const float* pw2 = (const float*)d_in[15];
    const float* pb2 = (const float*)d_in[16];
    const float* vw1 = (const float*)d_in[17];
    const float* vb1 = (const float*)d_in[18];
    const float* vw2 = (const float*)d_in[19];
    const float* vb2 = (const float*)d_in[20];

    float* out_logits = (float*)d_out;
    float* out_v      = (float*)d_out + TB * NACT;
    float* out_state  = (float*)d_out + TB * NACT + TB;

    static int attr_done = 0;
    if (!attr_done) {
        cudaFuncSetAttribute(k_conv1, cudaFuncAttributeMaxDynamicSharedMemorySize, 73856);
        cudaFuncSetAttribute(k_conv2, cudaFuncAttributeMaxDynamicSharedMemorySize, 61824);
        cudaFuncSetAttribute(k_conv3, cudaFuncAttributeMaxDynamicSharedMemorySize, 46336);
        attr_done = 1;
    }

    // independent preambles
    k_codes <<<1, 32>>>(pos, done);
    k_zero  <<<32, 128>>>();
    k_acc0  <<<517, 256>>>(pw1, vw1, state0);
    k_transW2<<<FLAT / 32, 256>>>(pw1, vw1);
    k_transFC<<<dim3(32, 16), dim3(32, 32)>>>(fcw);

    // CNN feature path
    k_conv1<<<TB, 384, 73856>>>(image, c1w, c1b);
    k_conv2<<<TB / 4, 384, 61824>>>(c2w, c2b);
    k_conv3<<<TB / 4, 256, 46336>>>(c3w, c3b);
    k_fc2  <<<dim3(16, 8), 256>>>(fcb);
    k_onehot<<<(TB * NACT + 255) / 256, 256>>>(lact);

    // parallel head contributions + tiny sequential finish
    k_dots   <<<TB, 256>>>(state0);
    k_scanfin<<<B_, 128>>>(done, pb1, vb1, pw2, pb2, vw2, vb2, out_logits, out_v);

    // final state reconstruction
    k_final<<<dim3(FLAT / 256, B_), 256>>>(state0, out_state);

    (void)in_sizes; (void)n_in; (void)out_size;
}

// round 5
// speedup vs baseline: 3.9097x; 1.0444x over previous
#include <cuda_runtime.h>
#include <cuda_bf16.h>

#define T_ 32
#define B_ 32
#define TB 1024
#define MAP 517
#define FLAT 132352   // 517*256
#define NACT 5
#define WCELL 66176   // 517*128 floats per cell

typedef unsigned long long u64;

// ---- packed f32x2 helpers (sm_103a FFMA2 path) ----
__device__ __forceinline__ u64 pack2(float lo, float hi) {
    u64 r;
    asm("mov.b64 %0, {%1, %2};" : "=l"(r) : "f"(lo), "f"(hi));
    return r;
}
__device__ __forceinline__ u64 fma2(u64 a, u64 b, u64 c) {
    u64 d;
    asm("fma.rn.f32x2 %0, %1, %2, %3;" : "=l"(d) : "l"(a), "l"(b), "l"(c));
    return d;
}
__device__ __forceinline__ void unpack2(u64 v, float& lo, float& hi) {
    asm("mov.b64 {%0, %1}, %2;" : "=f"(lo), "=f"(hi) : "l"(v));
}

// ---------------- scratch (device globals) ----------------
__device__ float g_Wt[FLAT * 128];      // [cell][k][j]
__device__ float g_fcwt[1024 * 512];    // [k][j]
__device__ float g_c1o[TB * 32 * 225];
__device__ float g_c2o[TB * 64 * 36];
__device__ float g_c3o[TB * 1024];
__device__ float g_h[TB * MAP];
__device__ float g_acc0[B_ * 128];
__device__ int   g_lastw[B_ * 256];
__device__ int   g_cell[TB];
__device__ int   g_code[TB];
__device__ float g_c[TB * 128];

// ======== transpose big head weights into [cell][k][j] ========
__global__ __launch_bounds__(256) void k_transW2(const float* __restrict__ pol,
                                                 const float* __restrict__ val) {
    __shared__ float tile[32][132];
    int f0 = blockIdx.x * 32;
    int tid = threadIdx.x;
    #pragma unroll
    for (int rep = 0; rep < 4; rep++) {
        int idx = tid + rep * 256;
        int j = idx >> 3, f4 = idx & 7;
        const float* src = (j < 64) ? (pol + (size_t)j * FLAT)
                                    : (val + (size_t)(j - 64) * FLAT);
        float4 v = *(const float4*)(src + f0 + f4 * 4);
        tile[f4 * 4 + 0][j] = v.x;
        tile[f4 * 4 + 1][j] = v.y;
        tile[f4 * 4 + 2][j] = v.z;
        tile[f4 * 4 + 3][j] = v.w;
    }
    __syncthreads();
    #pragma unroll
    for (int rep = 0; rep < 4; rep++) {
        int idx = tid + rep * 256;
        int fr = idx >> 5, jg = idx & 31;
        int f = f0 + fr;
        int cell = f & 255, k = f >> 8;
        float4 w = *(const float4*)&tile[fr][jg * 4];
        *(float4*)(g_Wt + (size_t)cell * WCELL + k * 128 + jg * 4) = w;
    }
}

// ---------------- transpose fc weights ----------------
__global__ void k_transFC(const float* __restrict__ fcw) {
    __shared__ float tile[32][33];
    int k = blockIdx.x * 32 + threadIdx.x;
    int j = blockIdx.y * 32 + threadIdx.y;
    tile[threadIdx.y][threadIdx.x] = fcw[j * 1024 + k];
    __syncthreads();
    int ko = blockIdx.x * 32 + threadIdx.y;
    int jo = blockIdx.y * 32 + threadIdx.x;
    g_fcwt[ko * 512 + jo] = tile[threadIdx.x][threadIdx.y];
}

// ================= conv1: (3,64,64) k8 s4 -> (32,15,15), relu ==================
__global__ __launch_bounds__(384) void k_conv1(const float* __restrict__ img,
                                               const float* __restrict__ w,
                                               const float* __restrict__ bias) {
    extern __shared__ float sh[];
    float* simg = sh;                 // 12288
    float* swt  = sh + 12288;         // [32][193]
    int ib = blockIdx.x;
    int tid = threadIdx.x;
    const float4* ip4 = (const float4*)(img + (size_t)ib * 12288);
    for (int i = tid; i < 3072; i += 384) ((float4*)simg)[i] = ip4[i];
    for (int i = tid; i < 6144; i += 384) {
        int oc = i / 192, kk = i % 192;
        swt[oc * 193 + kk] = w[i];
    }
    __syncthreads();

    int ocg = tid & 7;
    int ntile = tid >> 3;
    bool active = (ntile < 45);
    int oy = ntile / 3, oxb = (ntile % 3) * 5;
    int ibase = active ? (oy * 256 + oxb * 4) : 0;

    u64 acc2[4][2];
    float acc1[4];
    #pragma unroll
    for (int m = 0; m < 4; m++) {
        acc2[m][0] = 0ull; acc2[m][1] = 0ull; acc1[m] = 0.f;
    }

    const float* wrow0 = swt + (ocg * 4) * 193;
    #pragma unroll
    for (int c = 0; c < 3; c++) {
        #pragma unroll
        for (int ky = 0; ky < 8; ky++) {
            int off = c * 4096 + ky * 64 + ibase;
            float row[24];
            #pragma unroll
            for (int q = 0; q < 6; q++) {
                float4 v = *(const float4*)&simg[off + q * 4];
                row[q * 4 + 0] = v.x; row[q * 4 + 1] = v.y;
                row[q * 4 + 2] = v.z; row[q * 4 + 3] = v.w;
            }
            int kb = c * 64 + ky * 8;
            #pragma unroll
            for (int kx = 0; kx < 8; kx++) {
                u64 r0 = pack2(row[kx], row[kx + 4]);
                u64 r1 = pack2(row[kx + 8], row[kx + 12]);
                float r2 = row[kx + 16];
                #pragma unroll
                for (int m = 0; m < 4; m++) {
                    float wv = wrow0[m * 193 + kb + kx];
                    u64 wp = pack2(wv, wv);
                    acc2[m][0] = fma2(wp, r0, acc2[m][0]);
                    acc2[m][1] = fma2(wp, r1, acc2[m][1]);
                    acc1[m] += wv * r2;
                }
            }
        }
    }
    if (active) {
        #pragma unroll
        for (int m = 0; m < 4; m++) {
            int oc = ocg * 4 + m;
            float bb = bias[oc];
            float a0, a1, a2, a3;
            unpack2(acc2[m][0], a0, a1);
            unpack2(acc2[m][1], a2, a3);
            float* outp = g_c1o + (size_t)ib * 7200 + oc * 225 + oy * 15 + oxb;
            outp[0] = fmaxf(a0 + bb, 0.f);
            outp[1] = fmaxf(a1 + bb, 0.f);
            outp[2] = fmaxf(a2 + bb, 0.f);
            outp[3] = fmaxf(a3 + bb, 0.f);
            outp[4] = fmaxf(acc1[m] + bb, 0.f);
        }
    }
}

// ================= conv2: (32,15,15) k4 s2 -> (64,6,6), relu ==================
// smem input layout padded: [img][ic][y*16+x], ic chunked (8 per cb)
__global__ __launch_bounds__(384) void k_conv2(const float* __restrict__ w,
                                               const float* __restrict__ bias) {
    extern __shared__ float sh[];
    float* sin_ = sh;            // 4 img * 8 ic * 240 = 7680
    float* swt  = sh + 7680;     // [64][129] = 8256
    int ib4 = blockIdx.x;
    int tid = threadIdx.x;

    int ocg = tid & 15;
    int ntile = tid >> 4;
    int img_l = ntile / 6, oy = ntile % 6;

    u64 acc2[4][3];
    #pragma unroll
    for (int m = 0; m < 4; m++)
        #pragma unroll
        for (int p = 0; p < 3; p++) acc2[m][p] = 0ull;

    for (int cb = 0; cb < 4; cb++) {
        __syncthreads();
        for (int i = tid; i < 7200; i += 384) {
            int img = i / 1800, rem = i % 1800;
            int ic = rem / 225, r2 = rem % 225;
            int y = r2 / 15, x = r2 % 15;
            sin_[img * 1920 + ic * 240 + y * 16 + x] =
                g_c1o[(size_t)ib4 * 28800 + img * 7200 + cb * 1800 + rem];
        }
        for (int i = tid; i < 8192; i += 384) {
            int oc = i >> 7, kk = i & 127;
            swt[oc * 129 + kk] = w[oc * 512 + cb * 128 + kk];
        }
        __syncthreads();
        const float* wrow0 = swt + (ocg * 4) * 129;
        int base_in = img_l * 1920;
        #pragma unroll
        for (int icl = 0; icl < 8; icl++) {
            int pbase = base_in + icl * 240;
            #pragma unroll
            for (int ky = 0; ky < 4; ky++) {
                int off = pbase + (oy * 2 + ky) * 16;
                float row[14];
                #pragma unroll
                for (int q = 0; q < 3; q++) {
                    float4 v = *(const float4*)&sin_[off + q * 4];
                    row[q * 4 + 0] = v.x; row[q * 4 + 1] = v.y;
                    row[q * 4 + 2] = v.z; row[q * 4 + 3] = v.w;
                }
                row[12] = sin_[off + 12];
                row[13] = sin_[off + 13];
                int kb = icl * 16 + ky * 4;
                #pragma unroll
                for (int kx = 0; kx < 4; kx++) {
                    u64 r0 = pack2(row[kx], row[kx + 2]);
                    u64 r1 = pack2(row[kx + 4], row[kx + 6]);
                    u64 r2 = pack2(row[kx + 8], row[kx + 10]);
                    #pragma unroll
                    for (int m = 0; m < 4; m++) {
                        float wv = wrow0[m * 129 + kb + kx];
                        u64 wp = pack2(wv, wv);
                        acc2[m][0] = fma2(wp, r0, acc2[m][0]);
                        acc2[m][1] = fma2(wp, r1, acc2[m][1]);
                        acc2[m][2] = fma2(wp, r2, acc2[m][2]);
                    }
                }
            }
        }
    }
    int ib = ib4 * 4 + img_l;
    #pragma unroll
    for (int m = 0; m < 4; m++) {
        int oc = ocg * 4 + m;
        float bb = bias[oc];
        float* outp = g_c2o + (size_t)ib * 2304 + oc * 36 + oy * 6;
        #pragma unroll
        for (int p = 0; p < 3; p++) {
            float lo, hi;
            unpack2(acc2[m][p], lo, hi);
            outp[p * 2 + 0] = fmaxf(lo + bb, 0.f);
            outp[p * 2 + 1] = fmaxf(hi + bb, 0.f);
        }
    }
}

// ================= conv3: (64,6,6) k3 s1 -> (64,4,4), relu ==================
// smem input layout padded: [img][ic][y*8+x]
__global__ __launch_bounds__(256) void k_conv3(const float* __restrict__ w,
                                               const float* __restrict__ bias) {
    extern __shared__ float sh[];
    float* sin_ = sh;            // 4 img * 16 ic * 48 = 3072
    float* swt  = sh + 3072;     // [64][145] = 9280
    int ib4 = blockIdx.x;
    int tid = threadIdx.x;

    int ocg = tid & 15;
    int ntile = tid >> 4;
    int img_l = ntile >> 2, oy = ntile & 3;

    u64 acc2[4][2];
    #pragma unroll
    for (int m = 0; m < 4; m++) { acc2[m][0] = 0ull; acc2[m][1] = 0ull; }

    for (int cb = 0; cb < 4; cb++) {
        __syncthreads();
        for (int i = tid; i < 2304; i += 256) {
            int img = i / 576, rem = i % 576;
            int ic = rem / 36, r2 = rem % 36;
            int y = r2 / 6, x = r2 % 6;
            sin_[img * 768 + ic * 48 + y * 8 + x] =
                g_c2o[(size_t)ib4 * 9216 + img * 2304 + cb * 576 + rem];
        }
        for (int i = tid; i < 9216; i += 256) {
            int oc = i / 144, kk = i % 144;
            swt[oc * 145 + kk] = w[oc * 576 + cb * 144 + kk];
        }
        __syncthreads();
        const float* wrow0 = swt + (ocg * 4) * 145;
        int base_in = img_l * 768;
        #pragma unroll
        for (int icl = 0; icl < 16; icl++) {
            int pbase = base_in + icl * 48;
            #pragma unroll
            for (int ky = 0; ky < 3; ky++) {
                int off = pbase + (oy + ky) * 8;
                float row[6];
                float4 v = *(const float4*)&sin_[off];
                row[0] = v.x; row[1] = v.y; row[2] = v.z; row[3] = v.w;
                row[4] = sin_[off + 4];
                row[5] = sin_[off + 5];
                int kb = icl * 9 + ky * 3;
                #pragma unroll
                for (int kx = 0; kx < 3; kx++) {
                    u64 r0 = pack2(row[kx], row[kx + 1]);
                    u64 r1 = pack2(row[kx + 2], row[kx + 3]);
                    #pragma unroll
                    for (int m = 0; m < 4; m++) {
                        float wv = wrow0[m * 145 + kb + kx];
                        u64 wp = pack2(wv, wv);
                        acc2[m][0] = fma2(wp, r0, acc2[m][0]);
                        acc2[m][1] = fma2(wp, r1, acc2[m][1]);
                    }
                }
            }
        }
    }
    int ib = ib4 * 4 + img_l;
    #pragma unroll
    for (int m = 0; m < 4; m++) {
        int oc = ocg * 4 + m;
        float bb = bias[oc];
        float* outp = g_c3o + (size_t)ib * 1024 + oc * 16 + oy * 4;
        float a0, a1, a2, a3;
        unpack2(acc2[m][0], a0, a1);
        unpack2(acc2[m][1], a2, a3);
        outp[0] = fmaxf(a0 + bb, 0.f);
        outp[1] = fmaxf(a1 + bb, 0.f);
        outp[2] = fmaxf(a2 + bb, 0.f);
        outp[3] = fmaxf(a3 + bb, 0.f);
    }
}

// ================= fc: SGEMM 1024x512x1024 -> g_h (+relu) ==========
__global__ __launch_bounds__(256) void k_fc2(const float* __restrict__ bias) {
    __shared__ __align__(16) float Xs[32][72];   // [kk][img]
    __shared__ __align__(16) float Ws[32][64];   // [kk][oc]
    int i0 = blockIdx.x * 64;
    int j0 = blockIdx.y * 64;
    int tid = threadIdx.x;
    int im_g = tid & 15, oc_g = tid >> 4;

    u64 acc2[4][2];
    #pragma unroll
    for (int m = 0; m < 4; m++) { acc2[m][0] = 0ull; acc2[m][1] = 0ull; }

    for (int k0 = 0; k0 < 1024; k0 += 32) {
        __syncthreads();
        #pragma unroll
        for (int r = 0; r < 2; r++) {
            int idx = tid + 256 * r;          // < 512
            int im = idx & 63, kq = idx >> 6; // kq 0..7
            float4 v = *(const float4*)&g_c3o[(size_t)(i0 + im) * 1024 + k0 + kq * 4];
            Xs[kq * 4 + 0][im] = v.x;
            Xs[kq * 4 + 1][im] = v.y;
            Xs[kq * 4 + 2][im] = v.z;
            Xs[kq * 4 + 3][im] = v.w;
        }
        #pragma unroll
        for (int r = 0; r < 2; r++) {
            int idx = tid + 256 * r;          // < 512
            int kk = idx >> 4, oc4 = idx & 15;
            float4 v = *(const float4*)&g_fcwt[(size_t)(k0 + kk) * 512 + j0 + oc4 * 4];
            *(float4*)&Ws[kk][oc4 * 4] = v;
        }
        __syncthreads();
        #pragma unroll
        for (int kk = 0; kk < 32; kk++) {
            float4 wv = *(const float4*)&Ws[kk][oc_g * 4];
            float4 xv = *(const float4*)&Xs[kk][im_g * 4];
            u64 wp0 = pack2(wv.x, wv.y);
            u64 wp1 = pack2(wv.z, wv.w);
            u64 x0 = pack2(xv.x, xv.x);
            u64 x1 = pack2(xv.y, xv.y);
            u64 x2 = pack2(xv.z, xv.z);
            u64 x3 = pack2(xv.w, xv.w);
            acc2[0][0] = fma2(x0, wp0, acc2[0][0]);
            acc2[0][1] = fma2(x0, wp1, acc2[0][1]);
            acc2[1][0] = fma2(x1, wp0, acc2[1][0]);
            acc2[1][1] = fma2(x1, wp1, acc2[1][1]);
            acc2[2][0] = fma2(x2, wp0, acc2[2][0]);
            acc2[2][1] = fma2(x2, wp1, acc2[2][1]);
            acc2[3][0] = fma2(x3, wp0, acc2[3][0]);
            acc2[3][1] = fma2(x3, wp1, acc2[3][1]);
        }
    }
    #pragma unroll
    for (int m = 0; m < 4; m++) {
        int img = i0 + im_g * 4 + m;
        float a0, a1, a2, a3;
        unpack2(acc2[m][0], a0, a1);
        unpack2(acc2[m][1], a2, a3);
        int oc = j0 + oc_g * 4;
        g_h[(size_t)img * MAP + oc + 0] = fmaxf(a0 + bias[oc + 0], 0.f);
        g_h[(size_t)img * MAP + oc + 1] = fmaxf(a1 + bias[oc + 1], 0.f);
        g_h[(size_t)img * MAP + oc + 2] = fmaxf(a2 + bias[oc + 2], 0.f);
        g_h[(size_t)img * MAP + oc + 3] = fmaxf(a3 + bias[oc + 3], 0.f);
    }
}

// ---------------- onehot tail of g_h ----------------
__global__ void k_onehot(const int* __restrict__ lastact) {
    int i = blockIdx.x * 256 + threadIdx.x;
    if (i < TB * NACT) {
        int ib = i / NACT, a = i % NACT;
        g_h[(size_t)ib * MAP + 512 + a] = (lastact[ib] == a) ? 1.f : 0.f;
    }
}

// ---------------- zero acc0 ----------------
__global__ void k_zero() { g_acc0[blockIdx.x * 128 + threadIdx.x] = 0.f; }

// ======== acc0[j][b] = sum_f W[j][f]*s0[b][f] ========
__global__ __launch_bounds__(256) void k_acc0(const float* __restrict__ pol,
                                              const float* __restrict__ val,
                                              const float* __restrict__ s0) {
    __shared__ __align__(16) float Wt2[64][132];
    __shared__ __align__(16) float Ss[64][36];
    int kb0 = blockIdx.x * 256;
    int tid = threadIdx.x;
    int jg = tid >> 3;
    int bg = tid & 7;

    float acc[4][4];
    #pragma unroll
    for (int m = 0; m < 4; m++)
        #pragma unroll
        for (int n = 0; n < 4; n++) acc[m][n] = 0.f;

    for (int sub = 0; sub < 4; sub++) {
        int kbase = kb0 + sub * 64;
        __syncthreads();
        for (int i = tid; i < 8192; i += 256) {
            int kk = i & 63, j = i >> 6;
            const float* src = (j < 64) ? (pol + (size_t)j * FLAT)
                                        : (val + (size_t)(j - 64) * FLAT);
            Wt2[kk][j] = src[kbase + kk];
        }
        for (int i = tid; i < 2048; i += 256) {
            int kk = i & 63, b = i >> 6;
            Ss[kk][b] = s0[(size_t)b * FLAT + kbase + kk];
        }
        __syncthreads();
        #pragma unroll
        for (int kk = 0; kk < 64; kk++) {
            float4 wv = *(const float4*)&Wt2[kk][jg * 4];
            float4 sv = *(const float4*)&Ss[kk][bg * 4];
            acc[0][0] += wv.x * sv.x; acc[0][1] += wv.x * sv.y;
            acc[0][2] += wv.x * sv.z; acc[0][3] += wv.x * sv.w;
            acc[1][0] += wv.y * sv.x; acc[1][1] += wv.y * sv.y;
            acc[1][2] += wv.y * sv.z; acc[1][3] += wv.y * sv.w;
            acc[2][0] += wv.z * sv.x; acc[2][1] += wv.z * sv.y;
            acc[2][2] += wv.z * sv.z; acc[2][3] += wv.z * sv.w;
            acc[3][0] += wv.w * sv.x; acc[3][1] += wv.w * sv.y;
            acc[3][2] += wv.w * sv.z; acc[3][3] += wv.w * sv.w;
        }
    }
    #pragma unroll
    for (int m = 0; m < 4; m++)
        #pragma unroll
        for (int n = 0; n < 4; n++)
            atomicAdd(&g_acc0[(bg * 4 + n) * 128 + jg * 4 + m], acc[m][n]);
}

// ======== pass 1: integer last-writer scan ========
__global__ __launch_bounds__(32) void k_codes(const int* __restrict__ pos,
                                              const float* __restrict__ done) {
    __shared__ int lw[B_ * 256];
    int b = threadIdx.x;
    for (int c = 0; c < 256; c++) lw[b * 256 + c] = -2;
    for (int t = 0; t < T_; t++) {
        if (done[t * B_ + b] != 0.0f)
            for (int c = 0; c < 256; c++) lw[b * 256 + c] = -1;
        int r = t * B_ + b;
        int cell = pos[r * 2] * 16 + pos[r * 2 + 1];
        g_cell[r] = cell;
        g_code[r] = lw[b * 256 + cell];
        lw[b * 256 + cell] = t;
    }
    for (int c = 0; c < 256; c++) g_lastw[b * 256 + c] = lw[b * 256 + c];
}

// ======== pass 2: parallel per-(t,b) contribution dot products ========
__global__ __launch_bounds__(256) void k_dots(const float* __restrict__ s0) {
    __shared__ float delta[520];
    __shared__ float psum[8 * 128];
    int r = blockIdx.x;
    int b = r & 31;
    int tid = threadIdx.x;
    int cell = g_cell[r];
    int code = g_code[r];
    const float* hrow = g_h + (size_t)r * MAP;
    for (int k = tid; k < MAP; k += 256) {
        float old = 0.f;
        if (code >= 0)       old = g_h[(size_t)(code * B_ + b) * MAP + k];
        else if (code == -2) old = s0[(size_t)b * FLAT + k * 256 + cell];
        delta[k] = hrow[k] - old;
    }
    __syncthreads();
    int j4 = tid & 31;
    int kq = tid >> 5;
    const float* wb = g_Wt + (size_t)cell * WCELL + j4 * 4;
    float4 a = make_float4(0.f, 0.f, 0.f, 0.f);
    for (int k = kq; k < MAP; k += 8) {
        float4 w = *(const float4*)(wb + k * 128);
        float d = delta[k];
        a.x += w.x * d; a.y += w.y * d; a.z += w.z * d; a.w += w.w * d;
    }
    psum[kq * 128 + j4 * 4 + 0] = a.x;
    psum[kq * 128 + j4 * 4 + 1] = a.y;
    psum[kq * 128 + j4 * 4 + 2] = a.z;
    psum[kq * 128 + j4 * 4 + 3] = a.w;
    __syncthreads();
    if (tid < 128) {
        float s = 0.f;
        #pragma unroll
        for (int q = 0; q < 8; q++) s += psum[q * 128 + tid];
        g_c[(size_t)r * 128 + tid] = s;
    }
}

// ======== pass 3: prefix accumulate + tanh + head GEMVs ========
__global__ __launch_bounds__(128) void k_scanfin(const float* __restrict__ done,
                                                 const float* __restrict__ pb1,
                                                 const float* __restrict__ vb1,
                                                 const float* __restrict__ pw2,
                                                 const float* __restrict__ pb2,
                                                 const float* __restrict__ vw2,
                                                 const float* __restrict__ vb2,
                                                 float* __restrict__ logits,
                                                 float* __restrict__ vout) {
    __shared__ float th[128];
    int b = blockIdx.x;
    int tid = threadIdx.x;
    float accv = g_acc0[b * 128 + tid];
    float bb = (tid < 64) ? pb1[tid] : vb1[tid - 64];
    for (int t = 0; t < T_; t++) {
        int r = t * B_ + b;
        float dn = done[r];
        if (dn != 0.0f) accv = 0.f;
        accv += g_c[(size_t)r * 128 + tid];
        th[tid] = tanhf(accv + bb);
        __syncthreads();
        if (tid < NACT) {
            float s = pb2[tid];
            #pragma unroll
            for (int q = 0; q < 64; q++) s += th[q] * pw2[tid * 64 + q];
            logits[r * NACT + tid] = s;
        } else if (tid == 8) {
            float s = vb2[0];
            #pragma unroll
            for (int q = 0; q < 64; q++) s += th[64 + q] * vw2[q];
            vout[r] = s;
        }
        __syncthreads();
    }
}

// ---------------- reconstruct final_state ----------------
__global__ __launch_bounds__(256) void k_final(const float* __restrict__ s0,
                                               float* __restrict__ out) {
    int b = blockIdx.y;
    int f = blockIdx.x * 256 + threadIdx.x;
    int cell = f & 255, k = f >> 8;
    int code = g_lastw[b * 256 + cell];
    float v;
    if (code >= 0)       v = g_h[(size_t)(code * B_ + b) * MAP + k];
    else if (code == -2) v = s0[(size_t)b * FLAT + f];
    else                 v = 0.f;
    out[(size_t)b * FLAT + f] = v;
}

// ---------------- host ----------------
extern "C" void kernel_launch(void* const* d_in, const int* in_sizes, int n_in,
                              void* d_out, int out_size) {
    const float* image  = (const float*)d_in[0];
    const int*   lact   = (const int*)  d_in[1];
    const int*   pos    = (const int*)  d_in[2];
    const float* done   = (const float*)d_in[3];
    const float* state0 = (const float*)d_in[4];
    const float* c1w = (const float*)d_in[5];
    const float* c1b = (const float*)d_in[6];
    const float* c2w = (const float*)d_in[7];
    const float* c2b = (const float*)d_in[8];
    const float* c3w = (const float*)d_in[9];
    const float* c3b = (const float*)d_in[10];
    const float* fcw = (const float*)d_in[11];
    const float* fcb = (const float*)d_in[12];
    const float* pw1 = (const float*)d_in[13];
    const float* pb1 = (const float*)d_in[14];
    const float* pw2 = (const float*)d_in[15];
    const float* pb2 = (const float*)d_in[16];
    const float* vw1 = (const float*)d_in[17];
    const float* vb1 = (const float*)d_in[18];
    const float* vw2 = (const float*)d_in[19];
    const float* vb2 = (const float*)d_in[20];

    float* out_logits = (float*)d_out;
    float* out_v      = (float*)d_out + TB * NACT;
    float* out_state  = (float*)d_out + TB * NACT + TB;

    static cudaStream_t sA = nullptr, sB = nullptr;
    static cudaEvent_t ev0, evA, evB, evH, evFin;
    static int init_done = 0;
    if (!init_done) {
        cudaStreamCreateWithFlags(&sA, cudaStreamNonBlocking);
        cudaStreamCreateWithFlags(&sB, cudaStreamNonBlocking);
        cudaEventCreateWithFlags(&ev0,  cudaEventDisableTiming);
        cudaEventCreateWithFlags(&evA,  cudaEventDisableTiming);
        cudaEventCreateWithFlags(&evB,  cudaEventDisableTiming);
        cudaEventCreateWithFlags(&evH,  cudaEventDisableTiming);
        cudaEventCreateWithFlags(&evFin, cudaEventDisableTiming);
        cudaFuncSetAttribute(k_conv1, cudaFuncAttributeMaxDynamicSharedMemorySize, 73856);
        cudaFuncSetAttribute(k_conv2, cudaFuncAttributeMaxDynamicSharedMemorySize, 63744);
        cudaFuncSetAttribute(k_conv3, cudaFuncAttributeMaxDynamicSharedMemorySize, 49408);
        init_done = 1;
    }

    // fork side streams off the capture (default) stream
    cudaEventRecord(ev0, 0);
    cudaStreamWaitEvent(sA, ev0, 0);
    cudaStreamWaitEvent(sB, ev0, 0);

    // stream A: codes + acc0 (independent of conv path)
    k_codes<<<1, 32, 0, sA>>>(pos, done);
    k_zero <<<32, 128, 0, sA>>>();
    k_acc0 <<<517, 256, 0, sA>>>(pw1, vw1, state0);
    cudaEventRecord(evA, sA);

    // stream B: big weight transpose
    k_transW2<<<FLAT / 32, 256, 0, sB>>>(pw1, vw1);
    cudaEventRecord(evB, sB);

    // main stream: CNN feature path
    k_transFC<<<dim3(32, 16), dim3(32, 32)>>>(fcw);
    k_conv1<<<TB, 384, 73856>>>(image, c1w, c1b);
    k_conv2<<<TB / 4, 384, 63744>>>(c2w, c2b);
    k_conv3<<<TB / 4, 256, 49408>>>(c3w, c3b);
    k_fc2  <<<dim3(16, 8), 256>>>(fcb);
    k_onehot<<<(TB * NACT + 255) / 256, 256>>>(lact);
    cudaEventRecord(evH, 0);

    // final_state on stream B (overlaps dots/scanfin)
    cudaStreamWaitEvent(sB, evH, 0);
    cudaStreamWaitEvent(sB, evA, 0);
    k_final<<<dim3(FLAT / 256, B_), 256, 0, sB>>>(state0, out_state);
    cudaEventRecord(evFin, sB);

    // main stream: dots + sequential finish
    cudaStreamWaitEvent(0, evB, 0);
    cudaStreamWaitEvent(0, evA, 0);
    k_dots   <<<TB, 256>>>(state0);
    k_scanfin<<<B_, 128>>>(done, pb1, vb1, pw2, pb2, vw2, vb2, out_logits, out_v);

    // join stream B back before capture end
    cudaStreamWaitEvent(0, evFin, 0);

    (void)in_sizes; (void)n_in; (void)out_size;
}